// round 2
// baseline (speedup 1.0000x reference)
#include <cuda_runtime.h>
#include <math.h>

// Problem constants
#define BB 4
#define TT 4096
#define CC 1024
#define HS 128
#define MM (BB * TT)   // 16384 rows total

// ----------------------------------------------------------------------------
// Scratch (device globals -- no allocations allowed in kernel_launch)
// ----------------------------------------------------------------------------
__device__ float g_q[MM * HS];
__device__ float g_k[MM * HS];
__device__ float g_v[MM * HS];

// ----------------------------------------------------------------------------
// QKV projection: out = x @ W, x:(M,C) row-major, W:(C,HS) row-major
// Tile: 64 rows x 128 cols (full HS), K-tile 16. 256 threads, 4x8 micro-tile.
// blockIdx.y in {0,1,2} selects Wq/Wk/Wv -> g_q/g_k/g_v.
// ----------------------------------------------------------------------------
#define PM 64
#define PK 16

__global__ __launch_bounds__(256, 1)
void proj_kernel(const float* __restrict__ x,
                 const float* __restrict__ Wq,
                 const float* __restrict__ Wk,
                 const float* __restrict__ Wv)
{
    __shared__ float Xs[PM][PK];
    __shared__ float Ws[PK][HS];

    const float* W   = (blockIdx.y == 0) ? Wq : (blockIdx.y == 1) ? Wk : Wv;
    float*       out = (blockIdx.y == 0) ? g_q : (blockIdx.y == 1) ? g_k : g_v;

    const int row0 = blockIdx.x * PM;
    const int tid  = threadIdx.x;
    const int ty   = tid >> 4;       // 0..15
    const int tx   = tid & 15;       // 0..15
    const int r0   = ty * 4;         // 4 rows
    const int c0   = tx * 8;         // 8 cols

    float acc[4][8];
#pragma unroll
    for (int i = 0; i < 4; i++)
#pragma unroll
        for (int j = 0; j < 8; j++) acc[i][j] = 0.f;

    // X-tile load mapping: 64x16 floats = 256 float4, one per thread
    const int xr = tid >> 2;
    const int xk = (tid & 3) * 4;

    for (int k0 = 0; k0 < CC; k0 += PK) {
        *(float4*)&Xs[xr][xk] = *(const float4*)&x[(size_t)(row0 + xr) * CC + k0 + xk];

        // W-tile: 16x128 floats = 512 float4, 2 per thread
#pragma unroll
        for (int it = 0; it < 2; it++) {
            int f  = it * 256 + tid;
            int wk = f >> 5;
            int wn = (f & 31) * 4;
            *(float4*)&Ws[wk][wn] = *(const float4*)&W[(size_t)(k0 + wk) * HS + wn];
        }
        __syncthreads();

#pragma unroll
        for (int k = 0; k < PK; k++) {
            float a[4], b[8];
#pragma unroll
            for (int i = 0; i < 4; i++) a[i] = Xs[r0 + i][k];
#pragma unroll
            for (int j = 0; j < 8; j++) b[j] = Ws[k][c0 + j];
#pragma unroll
            for (int i = 0; i < 4; i++)
#pragma unroll
                for (int j = 0; j < 8; j++) acc[i][j] = fmaf(a[i], b[j], acc[i][j]);
        }
        __syncthreads();
    }

#pragma unroll
    for (int i = 0; i < 4; i++) {
        float* op = &out[(size_t)(row0 + r0 + i) * HS + c0];
#pragma unroll
        for (int j = 0; j < 8; j++) op[j] = acc[i][j];
    }
}

// ----------------------------------------------------------------------------
// Flash attention (causal), fp32. BM=BN=64, 256 threads.
// Online softmax with row stats in shared memory; O accumulators in registers.
// ----------------------------------------------------------------------------
#define BM 64
#define BN 64
#define QPAD 132   // 128 + 4 pad (keeps float4 alignment, kills bank conflicts)
#define SPAD 68    // 64 + 4 pad

#define ATTN_SMEM_FLOATS (BM * QPAD + BN * QPAD + BN * QPAD + BM * SPAD + 3 * BM)
#define ATTN_SMEM_BYTES  (ATTN_SMEM_FLOATS * 4)

__global__ __launch_bounds__(256, 1)
void attn_kernel(float* __restrict__ out)
{
    extern __shared__ float smem[];
    float* Qs    = smem;                    // [BM][QPAD]
    float* Ks    = Qs + BM * QPAD;          // [BN][QPAD]
    float* Vs    = Ks + BN * QPAD;          // [BN][QPAD]
    float* Ps    = Vs + BN * QPAD;          // [BM][SPAD]
    float* m_sh  = Ps + BM * SPAD;          // [BM]
    float* l_sh  = m_sh + BM;               // [BM]
    float* sc_sh = l_sh + BM;               // [BM]

    // Reverse tile order: heavy causal tiles (large bi) launch first
    const int bi = gridDim.x - 1 - blockIdx.x;
    const int b  = blockIdx.y;
    const int tid = threadIdx.x;

    const float* qp = g_q + (size_t)b * TT * HS;
    const float* kp = g_k + (size_t)b * TT * HS;
    const float* vp = g_v + (size_t)b * TT * HS;

    // Load Q tile: 64x128 = 2048 float4, 8 per thread
    for (int f = tid; f < BM * HS / 4; f += 256) {
        int r  = f >> 5;
        int cq = (f & 31) * 4;
        *(float4*)&Qs[r * QPAD + cq] =
            *(const float4*)&qp[(size_t)(bi * BM + r) * HS + cq];
    }
    if (tid < BM) { m_sh[tid] = -1e30f; l_sh[tid] = 0.f; }

    const int ty  = tid >> 4, tx = tid & 15;
    const int sr0 = ty * 4, sc0 = tx * 4;   // S micro-tile 4x4
    const int or0 = ty * 4, oc0 = tx * 8;   // O micro-tile 4x8

    float oacc[4][8];
#pragma unroll
    for (int i = 0; i < 4; i++)
#pragma unroll
        for (int j = 0; j < 8; j++) oacc[i][j] = 0.f;

    const float softmax_scale = 0.08838834764831845f;   // 1/sqrt(128)
    const int srow = tid >> 2;      // softmax pass: row per 4 threads
    const int sseg = tid & 3;       // 16 cols each

    for (int j = 0; j <= bi; j++) {
        __syncthreads();   // previous iter done with Ks/Vs/Ps; also covers Q load

        // Load K and V tiles
        for (int f = tid; f < BN * HS / 4; f += 256) {
            int r  = f >> 5;
            int cq = (f & 31) * 4;
            size_t g = (size_t)(j * BN + r) * HS + cq;
            *(float4*)&Ks[r * QPAD + cq] = *(const float4*)&kp[g];
            *(float4*)&Vs[r * QPAD + cq] = *(const float4*)&vp[g];
        }
        __syncthreads();

        // S = Q K^T (4x4 per thread over K=128)
        float s[4][4];
#pragma unroll
        for (int i = 0; i < 4; i++)
#pragma unroll
            for (int c = 0; c < 4; c++) s[i][c] = 0.f;

#pragma unroll 4
        for (int k = 0; k < HS; k++) {
            float a[4], bb[4];
#pragma unroll
            for (int i = 0; i < 4; i++) a[i]  = Qs[(sr0 + i) * QPAD + k];
#pragma unroll
            for (int c = 0; c < 4; c++) bb[c] = Ks[(sc0 + c) * QPAD + k];
#pragma unroll
            for (int i = 0; i < 4; i++)
#pragma unroll
                for (int c = 0; c < 4; c++) s[i][c] = fmaf(a[i], bb[c], s[i][c]);
        }

        // scale + causal mask + stage to Ps
        const bool diag = (j == bi);
#pragma unroll
        for (int i = 0; i < 4; i++)
#pragma unroll
            for (int c = 0; c < 4; c++) {
                float val = s[i][c] * softmax_scale;
                if (diag && (sc0 + c > sr0 + i)) val = -1e30f;
                Ps[(sr0 + i) * SPAD + sc0 + c] = val;
            }
        __syncthreads();

        // Online softmax pass: 4 threads per row (16 cols each), shfl reduce
        {
            float* prow = &Ps[srow * SPAD + sseg * 16];
            float mloc = -1e30f;
#pragma unroll
            for (int c = 0; c < 16; c++) mloc = fmaxf(mloc, prow[c]);
            mloc = fmaxf(mloc, __shfl_xor_sync(0xffffffffu, mloc, 1));
            mloc = fmaxf(mloc, __shfl_xor_sync(0xffffffffu, mloc, 2));

            float mold = m_sh[srow];
            float mnew = fmaxf(mold, mloc);
            float fact = __expf(mold - mnew);

            float ssum = 0.f;
#pragma unroll
            for (int c = 0; c < 16; c++) {
                float p = __expf(prow[c] - mnew);
                prow[c] = p;
                ssum += p;
            }
            ssum += __shfl_xor_sync(0xffffffffu, ssum, 1);
            ssum += __shfl_xor_sync(0xffffffffu, ssum, 2);

            if (sseg == 0) {
                m_sh[srow]  = mnew;
                l_sh[srow]  = l_sh[srow] * fact + ssum;
                sc_sh[srow] = fact;
            }
        }
        __syncthreads();

        // Rescale O and accumulate P @ V (4x8 per thread over 64)
        float fr[4];
#pragma unroll
        for (int i = 0; i < 4; i++) fr[i] = sc_sh[or0 + i];
#pragma unroll
        for (int i = 0; i < 4; i++)
#pragma unroll
            for (int jj = 0; jj < 8; jj++) oacc[i][jj] *= fr[i];

#pragma unroll 4
        for (int sI = 0; sI < BN; sI++) {
            float p[4];
#pragma unroll
            for (int i = 0; i < 4; i++) p[i] = Ps[(or0 + i) * SPAD + sI];
            float4 v0 = *(float4*)&Vs[sI * QPAD + oc0];
            float4 v1 = *(float4*)&Vs[sI * QPAD + oc0 + 4];
            float vv[8] = {v0.x, v0.y, v0.z, v0.w, v1.x, v1.y, v1.z, v1.w};
#pragma unroll
            for (int i = 0; i < 4; i++)
#pragma unroll
                for (int jj = 0; jj < 8; jj++)
                    oacc[i][jj] = fmaf(p[i], vv[jj], oacc[i][jj]);
        }
    }

    // Normalize and store
    float linv[4];
#pragma unroll
    for (int i = 0; i < 4; i++) linv[i] = 1.f / l_sh[or0 + i];
#pragma unroll
    for (int i = 0; i < 4; i++) {
        size_t grow = (size_t)b * TT + bi * BM + or0 + i;
        float* op = &out[grow * HS + oc0];
#pragma unroll
        for (int jj = 0; jj < 8; jj++) op[jj] = oacc[i][jj] * linv[i];
    }
}

// ----------------------------------------------------------------------------
// Launcher
// ----------------------------------------------------------------------------
extern "C" void kernel_launch(void* const* d_in, const int* in_sizes, int n_in,
                              void* d_out, int out_size)
{
    const float* x  = (const float*)d_in[0];
    const float* Wq = (const float*)d_in[1];
    const float* Wk = (const float*)d_in[2];
    const float* Wv = (const float*)d_in[3];
    float* out = (float*)d_out;

    // QKV projections
    dim3 pg(MM / PM, 3);
    proj_kernel<<<pg, 256>>>(x, Wq, Wk, Wv);

    // Flash attention (dynamic smem > 48KB needs the attribute; idempotent)
    cudaFuncSetAttribute(attn_kernel,
                         cudaFuncAttributeMaxDynamicSharedMemorySize,
                         ATTN_SMEM_BYTES);
    dim3 ag(TT / BM, BB);
    attn_kernel<<<ag, 256, ATTN_SMEM_BYTES>>>(out);
}

// round 4
// speedup vs baseline: 3.9938x; 3.9938x over previous
#include <cuda_runtime.h>
#include <math.h>

// Problem constants
#define BB 4
#define TT 4096
#define CC 1024
#define HS 128
#define MM (BB * TT)

// ----------------------------------------------------------------------------
// Scratch (device globals -- no allocations allowed)
// ----------------------------------------------------------------------------
__device__ float g_q[MM * HS];
__device__ float g_k[MM * HS];
__device__ float g_v[MM * HS];

// ----------------------------------------------------------------------------
// tf32 helpers
// ----------------------------------------------------------------------------
__device__ __forceinline__ unsigned f2tf(float x) {
    unsigned r; asm("cvt.rna.tf32.f32 %0, %1;" : "=r"(r) : "f"(x)); return r;
}
__device__ __forceinline__ float f2tff(float x) { return __uint_as_float(f2tf(x)); }

// D += A(16x8, row) * B(8x8, col), tf32 inputs, fp32 accum
__device__ __forceinline__ void mma8(float c[4],
                                     unsigned a0, unsigned a1, unsigned a2, unsigned a3,
                                     unsigned b0, unsigned b1) {
    asm volatile(
        "mma.sync.aligned.m16n8k8.row.col.f32.tf32.tf32.f32 "
        "{%0,%1,%2,%3},{%4,%5,%6,%7},{%8,%9},{%0,%1,%2,%3};"
        : "+f"(c[0]), "+f"(c[1]), "+f"(c[2]), "+f"(c[3])
        : "r"(a0), "r"(a1), "r"(a2), "r"(a3), "r"(b0), "r"(b1));
}

// ----------------------------------------------------------------------------
// QKV projection: out = x @ W  (M=16384, N=128, K=1024), tf32 tensor cores.
// CTA tile 128x128, K-tile 32. 8 warps: warp = m32 x n64.
// Outputs stored PRE-ROUNDED to tf32 so attention can skip cvt.
// ----------------------------------------------------------------------------
#define P_TM 128
#define P_TK 32
#define XSTR 36    // 32 + 4  (stride == 4 mod 32 -> conflict-free A frags)
#define WSTR 136   // 128 + 8 (stride == 8 mod 32 -> conflict-free B frags)

__global__ __launch_bounds__(256, 2)
void proj_kernel(const float* __restrict__ x,
                 const float* __restrict__ Wq,
                 const float* __restrict__ Wk,
                 const float* __restrict__ Wv)
{
    __shared__ float Xs[P_TM * XSTR];
    __shared__ float Wsm[P_TK * WSTR];

    const float* W   = (blockIdx.y == 0) ? Wq : (blockIdx.y == 1) ? Wk : Wv;
    float*       out = (blockIdx.y == 0) ? g_q : (blockIdx.y == 1) ? g_k : g_v;

    const int row0 = blockIdx.x * P_TM;
    const int tid  = threadIdx.x, lane = tid & 31, w = tid >> 5;
    const int m0   = (w >> 1) * 32;   // warp row offset (2 m16 frags)
    const int half = w & 1;           // warp col half (64 cols)

    float acc[2][8][4];
#pragma unroll
    for (int mf = 0; mf < 2; mf++)
#pragma unroll
        for (int f = 0; f < 8; f++)
#pragma unroll
            for (int r = 0; r < 4; r++) acc[mf][f][r] = 0.f;

    for (int kt = 0; kt < CC; kt += P_TK) {
        // X tile 128x32 (cvt to tf32)
        for (int f = tid; f < P_TM * P_TK / 4; f += 256) {
            int r = f >> 3, c = (f & 7) * 4;
            float4 v = *(const float4*)&x[(size_t)(row0 + r) * CC + kt + c];
            v.x = f2tff(v.x); v.y = f2tff(v.y); v.z = f2tff(v.z); v.w = f2tff(v.w);
            *(float4*)&Xs[r * XSTR + c] = v;
        }
        // W tile 32x128 (cvt to tf32)
        for (int f = tid; f < P_TK * HS / 4; f += 256) {
            int r = f >> 5, c = (f & 31) * 4;
            float4 v = *(const float4*)&W[(size_t)(kt + r) * HS + c];
            v.x = f2tff(v.x); v.y = f2tff(v.y); v.z = f2tff(v.z); v.w = f2tff(v.w);
            *(float4*)&Wsm[r * WSTR + c] = v;
        }
        __syncthreads();

#pragma unroll
        for (int ks = 0; ks < 4; ks++) {
            const int k0 = ks * 8;
            unsigned a[2][4];
#pragma unroll
            for (int mf = 0; mf < 2; mf++) {
                int ar = m0 + mf * 16 + (lane >> 2);
                int ac = k0 + (lane & 3);
                a[mf][0] = __float_as_uint(Xs[ar * XSTR + ac]);
                a[mf][1] = __float_as_uint(Xs[(ar + 8) * XSTR + ac]);
                a[mf][2] = __float_as_uint(Xs[ar * XSTR + ac + 4]);
                a[mf][3] = __float_as_uint(Xs[(ar + 8) * XSTR + ac + 4]);
            }
#pragma unroll
            for (int f = 0; f < 8; f++) {
                int bc = half * 64 + f * 8 + (lane >> 2);
                unsigned b0 = __float_as_uint(Wsm[(k0 + (lane & 3)) * WSTR + bc]);
                unsigned b1 = __float_as_uint(Wsm[(k0 + 4 + (lane & 3)) * WSTR + bc]);
                mma8(acc[0][f], a[0][0], a[0][1], a[0][2], a[0][3], b0, b1);
                mma8(acc[1][f], a[1][0], a[1][1], a[1][2], a[1][3], b0, b1);
            }
        }
        __syncthreads();
    }

    // Write out, pre-rounded to tf32
#pragma unroll
    for (int mf = 0; mf < 2; mf++) {
        int r = row0 + m0 + mf * 16 + (lane >> 2);
#pragma unroll
        for (int f = 0; f < 8; f++) {
            int c = half * 64 + f * 8 + 2 * (lane & 3);
            *(float2*)&out[(size_t)r * HS + c] =
                make_float2(f2tff(acc[mf][f][0]), f2tff(acc[mf][f][1]));
            *(float2*)&out[(size_t)(r + 8) * HS + c] =
                make_float2(f2tff(acc[mf][f][2]), f2tff(acc[mf][f][3]));
        }
    }
}

// ----------------------------------------------------------------------------
// Flash attention (causal), tf32 tensor cores.
// BM=BN=64, 256 threads (8 warps). Each CTA processes the balanced q-tile
// pair (qi, 63-qi): constant 65 K-iterations per CTA.
// S phase: warp = 16 rows x 32-col half. PV phase: warp = 16 rows x 64-hs half.
// ----------------------------------------------------------------------------
#define QSTR 132   // == 4 mod 32
#define VSTR 136   // == 8 mod 32
#define PSTR 68    // == 4 mod 32

#define SM_QS   0
#define SM_KS   (SM_QS + 64 * QSTR)
#define SM_VS   (SM_KS + 64 * QSTR)
#define SM_PS   (SM_VS + 64 * VSTR)
#define SM_PMAX (SM_PS + 64 * PSTR)
#define SM_PSUM (SM_PMAX + 128)
#define SM_M    (SM_PSUM + 128)
#define SM_L    (SM_M + 64)
#define SM_TOT  (SM_L + 64)
#define ATTN_SMEM_BYTES (SM_TOT * 4)

__global__ __launch_bounds__(256, 1)
void attn_kernel(float* __restrict__ out)
{
    extern __shared__ float sm[];
    float* Qs   = sm + SM_QS;
    float* Ks   = sm + SM_KS;
    float* Vs   = sm + SM_VS;
    float* Ps   = sm + SM_PS;
    float* pmax = sm + SM_PMAX;
    float* psum = sm + SM_PSUM;
    float* m_sh = sm + SM_M;
    float* l_sh = sm + SM_L;

    const int tid = threadIdx.x, lane = tid & 31, w = tid >> 5;
    const int rg = w >> 1;     // row group: 16 rows
    const int half = w & 1;    // col half
    const int b = blockIdx.y;
    const float scale = 0.08838834764831845f;  // 1/sqrt(128)

    const float* qb = g_q + (size_t)b * TT * HS;
    const float* kb = g_k + (size_t)b * TT * HS;
    const float* vb = g_v + (size_t)b * TT * HS;

    const int r0 = rg * 16 + (lane >> 2);
    const int r1 = r0 + 8;

    for (int phase = 0; phase < 2; phase++) {
        const int qi = phase ? (63 - (int)blockIdx.x) : (int)blockIdx.x;
        __syncthreads();

        // Load Q tile (fold softmax scale, round to tf32)
        const float* qg = qb + (size_t)qi * 64 * HS;
        for (int f = tid; f < 64 * HS / 4; f += 256) {
            int r = f >> 5, c = (f & 31) * 4;
            float4 v = *(const float4*)&qg[r * HS + c];
            v.x = f2tff(v.x * scale); v.y = f2tff(v.y * scale);
            v.z = f2tff(v.z * scale); v.w = f2tff(v.w * scale);
            *(float4*)&Qs[r * QSTR + c] = v;
        }
        if (tid < 64) { m_sh[tid] = -1e30f; l_sh[tid] = 0.f; }

        float o[8][4];
#pragma unroll
        for (int f = 0; f < 8; f++) { o[f][0] = o[f][1] = o[f][2] = o[f][3] = 0.f; }

        for (int j = 0; j <= qi; j++) {
            __syncthreads();   // prev iter done with Ks/Vs/Ps; Q load + stats visible
            // Load K and V tiles (already tf32-rounded in global)
            const float* kg = kb + (size_t)j * 64 * HS;
            const float* vg = vb + (size_t)j * 64 * HS;
            for (int f = tid; f < 64 * HS / 4; f += 256) {
                int r = f >> 5, c = (f & 31) * 4;
                *(float4*)&Ks[r * QSTR + c] = *(const float4*)&kg[r * HS + c];
                *(float4*)&Vs[r * VSTR + c] = *(const float4*)&vg[r * HS + c];
            }
            __syncthreads();

            // ---- S = Q K^T : warp computes 16 rows x 32 cols ----
            float s[4][4];
#pragma unroll
            for (int f = 0; f < 4; f++) { s[f][0] = s[f][1] = s[f][2] = s[f][3] = 0.f; }

#pragma unroll
            for (int ks = 0; ks < 16; ks++) {
                const int k0 = ks * 8;
                const int ac = k0 + (lane & 3);
                unsigned a0 = __float_as_uint(Qs[r0 * QSTR + ac]);
                unsigned a1 = __float_as_uint(Qs[r1 * QSTR + ac]);
                unsigned a2 = __float_as_uint(Qs[r0 * QSTR + ac + 4]);
                unsigned a3 = __float_as_uint(Qs[r1 * QSTR + ac + 4]);
#pragma unroll
                for (int f = 0; f < 4; f++) {
                    int bn = half * 32 + f * 8 + (lane >> 2);
                    unsigned b0 = __float_as_uint(Ks[bn * QSTR + k0 + (lane & 3)]);
                    unsigned b1 = __float_as_uint(Ks[bn * QSTR + k0 + 4 + (lane & 3)]);
                    mma8(s[f], a0, a1, a2, a3, b0, b1);
                }
            }

            // Causal mask (diagonal tile only)
            if (j == qi) {
#pragma unroll
                for (int f = 0; f < 4; f++) {
                    int c = half * 32 + f * 8 + 2 * (lane & 3);
                    if (c     > r0) s[f][0] = -1e30f;
                    if (c + 1 > r0) s[f][1] = -1e30f;
                    if (c     > r1) s[f][2] = -1e30f;
                    if (c + 1 > r1) s[f][3] = -1e30f;
                }
            }

            // Partial row max (per half), shfl over the 4-lane row group
            float rm0 = -1e30f, rm1 = -1e30f;
#pragma unroll
            for (int f = 0; f < 4; f++) {
                rm0 = fmaxf(rm0, fmaxf(s[f][0], s[f][1]));
                rm1 = fmaxf(rm1, fmaxf(s[f][2], s[f][3]));
            }
            rm0 = fmaxf(rm0, __shfl_xor_sync(0xffffffffu, rm0, 1));
            rm0 = fmaxf(rm0, __shfl_xor_sync(0xffffffffu, rm0, 2));
            rm1 = fmaxf(rm1, __shfl_xor_sync(0xffffffffu, rm1, 1));
            rm1 = fmaxf(rm1, __shfl_xor_sync(0xffffffffu, rm1, 2));
            if ((lane & 3) == 0) {
                pmax[half * 64 + r0] = rm0;
                pmax[half * 64 + r1] = rm1;
            }
            __syncthreads();

            // Online softmax: combine halves, exp, stage P to smem (tf32-rounded)
            float mold0 = m_sh[r0], mold1 = m_sh[r1];
            float mn0 = fmaxf(mold0, fmaxf(pmax[r0], pmax[64 + r0]));
            float mn1 = fmaxf(mold1, fmaxf(pmax[r1], pmax[64 + r1]));
            float f0 = __expf(mold0 - mn0), f1 = __expf(mold1 - mn1);
            float sum0 = 0.f, sum1 = 0.f;
#pragma unroll
            for (int f = 0; f < 4; f++) {
                int c = half * 32 + f * 8 + 2 * (lane & 3);
                float p00 = __expf(s[f][0] - mn0), p01 = __expf(s[f][1] - mn0);
                float p10 = __expf(s[f][2] - mn1), p11 = __expf(s[f][3] - mn1);
                sum0 += p00 + p01; sum1 += p10 + p11;
                *(float2*)&Ps[r0 * PSTR + c] = make_float2(f2tff(p00), f2tff(p01));
                *(float2*)&Ps[r1 * PSTR + c] = make_float2(f2tff(p10), f2tff(p11));
            }
            sum0 += __shfl_xor_sync(0xffffffffu, sum0, 1);
            sum0 += __shfl_xor_sync(0xffffffffu, sum0, 2);
            sum1 += __shfl_xor_sync(0xffffffffu, sum1, 1);
            sum1 += __shfl_xor_sync(0xffffffffu, sum1, 2);
            if ((lane & 3) == 0) {
                psum[half * 64 + r0] = sum0;
                psum[half * 64 + r1] = sum1;
            }

            // Rescale O accumulators (rows match PV mapping: r0/r1)
#pragma unroll
            for (int f = 0; f < 8; f++) {
                o[f][0] *= f0; o[f][1] *= f0; o[f][2] *= f1; o[f][3] *= f1;
            }
            __syncthreads();   // all Ps + psums visible

            // Stats update (one thread per row)
            if (tid < 64) {
                float mo = m_sh[tid];
                float mn = fmaxf(mo, fmaxf(pmax[tid], pmax[64 + tid]));
                l_sh[tid] = l_sh[tid] * __expf(mo - mn) + psum[tid] + psum[64 + tid];
                m_sh[tid] = mn;
            }

            // ---- O += P V : warp computes 16 rows x 64 hs-cols ----
#pragma unroll
            for (int ks = 0; ks < 8; ks++) {
                const int k0 = ks * 8;
                const int ac = k0 + (lane & 3);
                unsigned a0 = __float_as_uint(Ps[r0 * PSTR + ac]);
                unsigned a1 = __float_as_uint(Ps[r1 * PSTR + ac]);
                unsigned a2 = __float_as_uint(Ps[r0 * PSTR + ac + 4]);
                unsigned a3 = __float_as_uint(Ps[r1 * PSTR + ac + 4]);
#pragma unroll
                for (int f = 0; f < 8; f++) {
                    int bn = half * 64 + f * 8 + (lane >> 2);
                    unsigned b0 = __float_as_uint(Vs[(k0 + (lane & 3)) * VSTR + bn]);
                    unsigned b1 = __float_as_uint(Vs[(k0 + 4 + (lane & 3)) * VSTR + bn]);
                    mma8(o[f], a0, a1, a2, a3, b0, b1);
                }
            }
        }

        // Normalize and store
        __syncthreads();   // final l_sh update visible
        float li0 = 1.f / l_sh[r0];
        float li1 = 1.f / l_sh[r1];
        float* ob = out + ((size_t)b * TT + (size_t)qi * 64) * HS;
#pragma unroll
        for (int f = 0; f < 8; f++) {
            int c = half * 64 + f * 8 + 2 * (lane & 3);
            *(float2*)&ob[(size_t)r0 * HS + c] = make_float2(o[f][0] * li0, o[f][1] * li0);
            *(float2*)&ob[(size_t)r1 * HS + c] = make_float2(o[f][2] * li1, o[f][3] * li1);
        }
    }
}

// ----------------------------------------------------------------------------
// Launcher
// ----------------------------------------------------------------------------
extern "C" void kernel_launch(void* const* d_in, const int* in_sizes, int n_in,
                              void* d_out, int out_size)
{
    const float* x  = (const float*)d_in[0];
    const float* Wq = (const float*)d_in[1];
    const float* Wk = (const float*)d_in[2];
    const float* Wv = (const float*)d_in[3];
    float* out = (float*)d_out;

    dim3 pg(MM / P_TM, 3);
    proj_kernel<<<pg, 256>>>(x, Wq, Wk, Wv);

    cudaFuncSetAttribute(attn_kernel,
                         cudaFuncAttributeMaxDynamicSharedMemorySize,
                         ATTN_SMEM_BYTES);
    dim3 ag(32, BB);   // 32 balanced q-tile pairs x 4 batches = 128 CTAs
    attn_kernel<<<ag, 256, ATTN_SMEM_BYTES>>>(out);
}

// round 7
// speedup vs baseline: 6.1295x; 1.5348x over previous
#include <cuda_runtime.h>
#include <math.h>

// Problem constants
#define BB 4
#define TT 4096
#define CC 1024
#define HS 128
#define MM (BB * TT)

// ----------------------------------------------------------------------------
// Scratch (device globals -- no allocations allowed)
// ----------------------------------------------------------------------------
__device__ float g_q[MM * HS];
__device__ float g_k[MM * HS];
__device__ float g_v[MM * HS];

// ----------------------------------------------------------------------------
// tf32 / async helpers
// ----------------------------------------------------------------------------
__device__ __forceinline__ unsigned f2tf(float x) {
    unsigned r; asm("cvt.rna.tf32.f32 %0, %1;" : "=r"(r) : "f"(x)); return r;
}
__device__ __forceinline__ float f2tff(float x) { return __uint_as_float(f2tf(x)); }

__device__ __forceinline__ void mma8(float c[4],
                                     unsigned a0, unsigned a1, unsigned a2, unsigned a3,
                                     unsigned b0, unsigned b1) {
    asm volatile(
        "mma.sync.aligned.m16n8k8.row.col.f32.tf32.tf32.f32 "
        "{%0,%1,%2,%3},{%4,%5,%6,%7},{%8,%9},{%0,%1,%2,%3};"
        : "+f"(c[0]), "+f"(c[1]), "+f"(c[2]), "+f"(c[3])
        : "r"(a0), "r"(a1), "r"(a2), "r"(a3), "r"(b0), "r"(b1));
}

__device__ __forceinline__ void cpa16(float* smem_dst, const float* gsrc) {
    unsigned s = (unsigned)__cvta_generic_to_shared(smem_dst);
    asm volatile("cp.async.cg.shared.global [%0], [%1], 16;" :: "r"(s), "l"(gsrc));
}
#define CP_COMMIT() asm volatile("cp.async.commit_group;")
#define CP_WAIT0()  asm volatile("cp.async.wait_group 0;")
#define PAIR_BAR(id) asm volatile("bar.sync %0, 64;" :: "r"((id) + 1) : "memory")

// ----------------------------------------------------------------------------
// QKV projection: out = x @ W  (M=16384, N=128, K=1024), tf32 tensor cores.
// CTA tile 128x128, K-tile 32. 8 warps: warp = m32 x n64.
// Register double-buffering: next tile LDGs overlap current tile MMAs.
// Outputs stored PRE-ROUNDED to tf32 so attention can skip cvt.
// ----------------------------------------------------------------------------
#define P_TM 128
#define P_TK 32
#define XSTR 36    // 32 + 4  (== 4 mod 32 -> conflict-free A frags)
#define WSTR 136   // 128 + 8 (== 8 mod 32 -> conflict-free B frags)

__global__ __launch_bounds__(256, 2)
void proj_kernel(const float* __restrict__ x,
                 const float* __restrict__ Wq,
                 const float* __restrict__ Wk,
                 const float* __restrict__ Wv)
{
    __shared__ float Xs[P_TM * XSTR];
    __shared__ float Wsm[P_TK * WSTR];

    const float* W   = (blockIdx.y == 0) ? Wq : (blockIdx.y == 1) ? Wk : Wv;
    float*       out = (blockIdx.y == 0) ? g_q : (blockIdx.y == 1) ? g_k : g_v;

    const int row0 = blockIdx.x * P_TM;
    const int tid  = threadIdx.x, lane = tid & 31, w = tid >> 5;
    const int m0   = (w >> 1) * 32;
    const int half = w & 1;

    // staging regs for double buffer
    float4 xr[4], wr[4];
    const int xrr[4] = { (tid) >> 3, (tid + 256) >> 3, (tid + 512) >> 3, (tid + 768) >> 3 };
    const int xcc    = (tid & 7) * 4;
    const int wrr[4] = { (tid) >> 5, (tid + 256) >> 5, (tid + 512) >> 5, (tid + 768) >> 5 };
    const int wcc    = (tid & 31) * 4;

    auto load_regs = [&](int kt) {
#pragma unroll
        for (int it = 0; it < 4; it++)
            xr[it] = *(const float4*)&x[(size_t)(row0 + xrr[it]) * CC + kt + xcc];
#pragma unroll
        for (int it = 0; it < 4; it++)
            wr[it] = *(const float4*)&W[(size_t)(kt + wrr[it]) * HS + wcc];
    };
    auto store_smem = [&]() {
#pragma unroll
        for (int it = 0; it < 4; it++) {
            float4 v = xr[it];
            v.x = f2tff(v.x); v.y = f2tff(v.y); v.z = f2tff(v.z); v.w = f2tff(v.w);
            *(float4*)&Xs[xrr[it] * XSTR + xcc] = v;
        }
#pragma unroll
        for (int it = 0; it < 4; it++) {
            float4 v = wr[it];
            v.x = f2tff(v.x); v.y = f2tff(v.y); v.z = f2tff(v.z); v.w = f2tff(v.w);
            *(float4*)&Wsm[wrr[it] * WSTR + wcc] = v;
        }
    };

    float acc[2][8][4];
#pragma unroll
    for (int mf = 0; mf < 2; mf++)
#pragma unroll
        for (int f = 0; f < 8; f++)
#pragma unroll
            for (int r = 0; r < 4; r++) acc[mf][f][r] = 0.f;

    load_regs(0);
    for (int kt = 0; kt < CC; kt += P_TK) {
        store_smem();
        __syncthreads();
        if (kt + P_TK < CC) load_regs(kt + P_TK);   // overlap with MMAs below

#pragma unroll
        for (int ks = 0; ks < 4; ks++) {
            const int k0 = ks * 8;
            unsigned a[2][4];
#pragma unroll
            for (int mf = 0; mf < 2; mf++) {
                int ar = m0 + mf * 16 + (lane >> 2);
                int ac = k0 + (lane & 3);
                a[mf][0] = __float_as_uint(Xs[ar * XSTR + ac]);
                a[mf][1] = __float_as_uint(Xs[(ar + 8) * XSTR + ac]);
                a[mf][2] = __float_as_uint(Xs[ar * XSTR + ac + 4]);
                a[mf][3] = __float_as_uint(Xs[(ar + 8) * XSTR + ac + 4]);
            }
#pragma unroll
            for (int f = 0; f < 8; f++) {
                int bc = half * 64 + f * 8 + (lane >> 2);
                unsigned b0 = __float_as_uint(Wsm[(k0 + (lane & 3)) * WSTR + bc]);
                unsigned b1 = __float_as_uint(Wsm[(k0 + 4 + (lane & 3)) * WSTR + bc]);
                mma8(acc[0][f], a[0][0], a[0][1], a[0][2], a[0][3], b0, b1);
                mma8(acc[1][f], a[1][0], a[1][1], a[1][2], a[1][3], b0, b1);
            }
        }
        __syncthreads();
    }

#pragma unroll
    for (int mf = 0; mf < 2; mf++) {
        int r = row0 + m0 + mf * 16 + (lane >> 2);
#pragma unroll
        for (int f = 0; f < 8; f++) {
            int c = half * 64 + f * 8 + 2 * (lane & 3);
            *(float2*)&out[(size_t)r * HS + c] =
                make_float2(f2tff(acc[mf][f][0]), f2tff(acc[mf][f][1]));
            *(float2*)&out[(size_t)(r + 8) * HS + c] =
                make_float2(f2tff(acc[mf][f][2]), f2tff(acc[mf][f][3]));
        }
    }
}

// ----------------------------------------------------------------------------
// Flash attention (causal), tf32 tensor cores.
// BM=BN=64, 256 threads (8 warps). CTA processes balanced q-tile pair
// (qi, 63-qi): constant 65 K-iterations.
// cp.async double-buffered K/V; softmax coupling is pair-local (named bars);
// one CTA-wide barrier per iteration.
// ----------------------------------------------------------------------------
#define QSTR 132   // == 4 mod 32
#define VSTR 136   // == 8 mod 32
#define PSTR 68    // == 4 mod 32

#define SM_QS   0
#define SM_KS   (SM_QS + 64 * QSTR)                 // 2 buffers
#define SM_VS   (SM_KS + 2 * 64 * QSTR)             // 2 buffers
#define SM_PS   (SM_VS + 2 * 64 * VSTR)
#define SM_PMAX (SM_PS + 64 * PSTR)
#define SM_PSUM (SM_PMAX + 128)
#define SM_M    (SM_PSUM + 128)
#define SM_L    (SM_M + 64)
#define SM_TOT  (SM_L + 64)
#define ATTN_SMEM_BYTES (SM_TOT * 4)

__global__ __launch_bounds__(256, 1)
void attn_kernel(float* __restrict__ out)
{
    extern __shared__ float sm[];
    float* Qs   = sm + SM_QS;
    float* Ksb  = sm + SM_KS;
    float* Vsb  = sm + SM_VS;
    float* Ps   = sm + SM_PS;
    float* pmax = sm + SM_PMAX;
    float* psum = sm + SM_PSUM;
    float* m_sh = sm + SM_M;
    float* l_sh = sm + SM_L;

    const int tid = threadIdx.x, lane = tid & 31, w = tid >> 5;
    const int rg = w >> 1;     // pair id (16-row group)
    const int half = w & 1;
    const int b = blockIdx.y;
    const float scale = 0.08838834764831845f;  // 1/sqrt(128)

    const float* qb = g_q + (size_t)b * TT * HS;
    const float* kb = g_k + (size_t)b * TT * HS;
    const float* vb = g_v + (size_t)b * TT * HS;

    const int r0 = rg * 16 + (lane >> 2);
    const int r1 = r0 + 8;

    // cp.async mapping: 8 x 16B per thread per tensor
    const int cr = tid >> 5;          // base row (stride 8 over 'it'... below)
    const int ccol = (tid & 31) * 4;

    for (int phase = 0; phase < 2; phase++) {
        const int qi = phase ? (63 - (int)blockIdx.x) : (int)blockIdx.x;
        __syncthreads();   // previous phase fully done with all smem

        // Prologue: async K/V loads for j=0 into buffer 0
        {
            const float* kg = kb;  // j=0
            const float* vg = vb;
#pragma unroll
            for (int it = 0; it < 8; it++) {
                int r = cr + it * 8;
                cpa16(&Ksb[r * QSTR + ccol], &kg[(size_t)r * HS + ccol]);
                cpa16(&Vsb[r * VSTR + ccol], &vg[(size_t)r * HS + ccol]);
            }
            CP_COMMIT();
        }

        // Q tile (fold softmax scale, round to tf32)
        const float* qg = qb + (size_t)qi * 64 * HS;
        for (int f = tid; f < 64 * HS / 4; f += 256) {
            int r = f >> 5, c = (f & 31) * 4;
            float4 v = *(const float4*)&qg[r * HS + c];
            v.x = f2tff(v.x * scale); v.y = f2tff(v.y * scale);
            v.z = f2tff(v.z * scale); v.w = f2tff(v.w * scale);
            *(float4*)&Qs[r * QSTR + c] = v;
        }
        if (tid < 64) { m_sh[tid] = -1e30f; l_sh[tid] = 0.f; }

        float o[8][4];
#pragma unroll
        for (int f = 0; f < 8; f++) { o[f][0] = o[f][1] = o[f][2] = o[f][3] = 0.f; }

        for (int j = 0; j <= qi; j++) {
            const int cur = j & 1;
            float* Ks = Ksb + cur * 64 * QSTR;
            float* Vs = Vsb + cur * 64 * VSTR;

            CP_WAIT0();
            __syncthreads();   // buf cur filled everywhere; prev iter fully done

            // Issue next iteration's loads (overlap with compute)
            if (j < qi) {
                const float* kg = kb + (size_t)(j + 1) * 64 * HS;
                const float* vg = vb + (size_t)(j + 1) * 64 * HS;
                float* Kn = Ksb + (1 - cur) * 64 * QSTR;
                float* Vn = Vsb + (1 - cur) * 64 * VSTR;
#pragma unroll
                for (int it = 0; it < 8; it++) {
                    int r = cr + it * 8;
                    cpa16(&Kn[r * QSTR + ccol], &kg[(size_t)r * HS + ccol]);
                    cpa16(&Vn[r * VSTR + ccol], &vg[(size_t)r * HS + ccol]);
                }
                CP_COMMIT();
            }

            // ---- S = Q K^T : warp computes 16 rows x 32 cols ----
            float s[4][4];
#pragma unroll
            for (int f = 0; f < 4; f++) { s[f][0] = s[f][1] = s[f][2] = s[f][3] = 0.f; }

#pragma unroll
            for (int ks = 0; ks < 16; ks++) {
                const int k0 = ks * 8;
                const int ac = k0 + (lane & 3);
                unsigned a0 = __float_as_uint(Qs[r0 * QSTR + ac]);
                unsigned a1 = __float_as_uint(Qs[r1 * QSTR + ac]);
                unsigned a2 = __float_as_uint(Qs[r0 * QSTR + ac + 4]);
                unsigned a3 = __float_as_uint(Qs[r1 * QSTR + ac + 4]);
#pragma unroll
                for (int f = 0; f < 4; f++) {
                    int bn = half * 32 + f * 8 + (lane >> 2);
                    unsigned b0 = __float_as_uint(Ks[bn * QSTR + k0 + (lane & 3)]);
                    unsigned b1 = __float_as_uint(Ks[bn * QSTR + k0 + 4 + (lane & 3)]);
                    mma8(s[f], a0, a1, a2, a3, b0, b1);
                }
            }

            // Causal mask (diagonal tile only)
            if (j == qi) {
#pragma unroll
                for (int f = 0; f < 4; f++) {
                    int c = half * 32 + f * 8 + 2 * (lane & 3);
                    if (c     > r0) s[f][0] = -1e30f;
                    if (c + 1 > r0) s[f][1] = -1e30f;
                    if (c     > r1) s[f][2] = -1e30f;
                    if (c + 1 > r1) s[f][3] = -1e30f;
                }
            }

            // Partial row max (per half)
            float rm0 = -1e30f, rm1 = -1e30f;
#pragma unroll
            for (int f = 0; f < 4; f++) {
                rm0 = fmaxf(rm0, fmaxf(s[f][0], s[f][1]));
                rm1 = fmaxf(rm1, fmaxf(s[f][2], s[f][3]));
            }
            rm0 = fmaxf(rm0, __shfl_xor_sync(0xffffffffu, rm0, 1));
            rm0 = fmaxf(rm0, __shfl_xor_sync(0xffffffffu, rm0, 2));
            rm1 = fmaxf(rm1, __shfl_xor_sync(0xffffffffu, rm1, 1));
            rm1 = fmaxf(rm1, __shfl_xor_sync(0xffffffffu, rm1, 2));
            if ((lane & 3) == 0) {
                pmax[half * 64 + r0] = rm0;
                pmax[half * 64 + r1] = rm1;
            }
            PAIR_BAR(rg);   // both halves' pmax visible within the pair

            // Online softmax: combine halves, exp, stage P to smem (tf32)
            float mold0 = m_sh[r0], mold1 = m_sh[r1];
            float mn0 = fmaxf(mold0, fmaxf(pmax[r0], pmax[64 + r0]));
            float mn1 = fmaxf(mold1, fmaxf(pmax[r1], pmax[64 + r1]));
            float f0 = __expf(mold0 - mn0), f1 = __expf(mold1 - mn1);
            float sum0 = 0.f, sum1 = 0.f;
#pragma unroll
            for (int f = 0; f < 4; f++) {
                int c = half * 32 + f * 8 + 2 * (lane & 3);
                float p00 = __expf(s[f][0] - mn0), p01 = __expf(s[f][1] - mn0);
                float p10 = __expf(s[f][2] - mn1), p11 = __expf(s[f][3] - mn1);
                sum0 += p00 + p01; sum1 += p10 + p11;
                *(float2*)&Ps[r0 * PSTR + c] = make_float2(f2tff(p00), f2tff(p01));
                *(float2*)&Ps[r1 * PSTR + c] = make_float2(f2tff(p10), f2tff(p11));
            }
            sum0 += __shfl_xor_sync(0xffffffffu, sum0, 1);
            sum0 += __shfl_xor_sync(0xffffffffu, sum0, 2);
            sum1 += __shfl_xor_sync(0xffffffffu, sum1, 1);
            sum1 += __shfl_xor_sync(0xffffffffu, sum1, 2);
            if ((lane & 3) == 0) {
                psum[half * 64 + r0] = sum0;
                psum[half * 64 + r1] = sum1;
            }

            // Rescale O accumulators
#pragma unroll
            for (int f = 0; f < 8; f++) {
                o[f][0] *= f0; o[f][1] *= f0; o[f][2] *= f1; o[f][3] *= f1;
            }
            PAIR_BAR(rg);   // all Ps + psum of the pair visible

            // Row stats update (pair-local: half0 row-leader lanes own 2 rows)
            if (half == 0 && (lane & 3) == 0) {
#pragma unroll
                for (int rr = 0; rr < 2; rr++) {
                    int r = rr ? r1 : r0;
                    float mo = m_sh[r];
                    float mn = fmaxf(mo, fmaxf(pmax[r], pmax[64 + r]));
                    l_sh[r] = l_sh[r] * __expf(mo - mn) + psum[r] + psum[64 + r];
                    m_sh[r] = mn;
                }
            }

            // ---- O += P V : warp computes 16 rows x 64 hs-cols ----
#pragma unroll
            for (int ks = 0; ks < 8; ks++) {
                const int k0 = ks * 8;
                const int ac = k0 + (lane & 3);
                unsigned a0 = __float_as_uint(Ps[r0 * PSTR + ac]);
                unsigned a1 = __float_as_uint(Ps[r1 * PSTR + ac]);
                unsigned a2 = __float_as_uint(Ps[r0 * PSTR + ac + 4]);
                unsigned a3 = __float_as_uint(Ps[r1 * PSTR + ac + 4]);
#pragma unroll
                for (int f = 0; f < 8; f++) {
                    int bn = half * 64 + f * 8 + (lane >> 2);
                    unsigned b0 = __float_as_uint(Vs[(k0 + (lane & 3)) * VSTR + bn]);
                    unsigned b1 = __float_as_uint(Vs[(k0 + 4 + (lane & 3)) * VSTR + bn]);
                    mma8(o[f], a0, a1, a2, a3, b0, b1);
                }
            }
        }

        // Normalize and store (pair-local stats -> pair barrier suffices)
        PAIR_BAR(rg);
        float li0 = 1.f / l_sh[r0];
        float li1 = 1.f / l_sh[r1];
        float* ob = out + ((size_t)b * TT + (size_t)qi * 64) * HS;
#pragma unroll
        for (int f = 0; f < 8; f++) {
            int c = half * 64 + f * 8 + 2 * (lane & 3);
            *(float2*)&ob[(size_t)r0 * HS + c] = make_float2(o[f][0] * li0, o[f][1] * li0);
            *(float2*)&ob[(size_t)r1 * HS + c] = make_float2(o[f][2] * li1, o[f][3] * li1);
        }
    }
}

// ----------------------------------------------------------------------------
// Launcher
// ----------------------------------------------------------------------------
extern "C" void kernel_launch(void* const* d_in, const int* in_sizes, int n_in,
                              void* d_out, int out_size)
{
    const float* x  = (const float*)d_in[0];
    const float* Wq = (const float*)d_in[1];
    const float* Wk = (const float*)d_in[2];
    const float* Wv = (const float*)d_in[3];
    float* out = (float*)d_out;

    dim3 pg(MM / P_TM, 3);
    proj_kernel<<<pg, 256>>>(x, Wq, Wk, Wv);

    cudaFuncSetAttribute(attn_kernel,
                         cudaFuncAttributeMaxDynamicSharedMemorySize,
                         ATTN_SMEM_BYTES);
    dim3 ag(32, BB);   // 32 balanced q-tile pairs x 4 batches = 128 CTAs
    attn_kernel<<<ag, 256, ATTN_SMEM_BYTES>>>(out);
}

// round 8
// speedup vs baseline: 8.7114x; 1.4212x over previous
#include <cuda_runtime.h>
#include <cuda_fp16.h>
#include <math.h>

// Problem constants
#define BB 4
#define TT 4096
#define CC 1024
#define HS 128
#define MM (BB * TT)

// ----------------------------------------------------------------------------
// Scratch (device globals -- no allocations allowed). fp16 q/k/v.
// ----------------------------------------------------------------------------
__device__ __half g_q[MM * HS];   // pre-scaled by 1/sqrt(HS)
__device__ __half g_k[MM * HS];
__device__ __half g_v[MM * HS];

// ----------------------------------------------------------------------------
// helpers
// ----------------------------------------------------------------------------
__device__ __forceinline__ unsigned f2tf(float x) {
    unsigned r; asm("cvt.rna.tf32.f32 %0, %1;" : "=r"(r) : "f"(x)); return r;
}
__device__ __forceinline__ float f2tff(float x) { return __uint_as_float(f2tf(x)); }

// tf32 mma (projection)
__device__ __forceinline__ void mma8(float c[4],
                                     unsigned a0, unsigned a1, unsigned a2, unsigned a3,
                                     unsigned b0, unsigned b1) {
    asm volatile(
        "mma.sync.aligned.m16n8k8.row.col.f32.tf32.tf32.f32 "
        "{%0,%1,%2,%3},{%4,%5,%6,%7},{%8,%9},{%0,%1,%2,%3};"
        : "+f"(c[0]), "+f"(c[1]), "+f"(c[2]), "+f"(c[3])
        : "r"(a0), "r"(a1), "r"(a2), "r"(a3), "r"(b0), "r"(b1));
}

// fp16 mma (attention), fp32 accum
__device__ __forceinline__ void mma16(float c[4],
                                      unsigned a0, unsigned a1, unsigned a2, unsigned a3,
                                      unsigned b0, unsigned b1) {
    asm volatile(
        "mma.sync.aligned.m16n8k16.row.col.f32.f16.f16.f32 "
        "{%0,%1,%2,%3},{%4,%5,%6,%7},{%8,%9},{%0,%1,%2,%3};"
        : "+f"(c[0]), "+f"(c[1]), "+f"(c[2]), "+f"(c[3])
        : "r"(a0), "r"(a1), "r"(a2), "r"(a3), "r"(b0), "r"(b1));
}

__device__ __forceinline__ void ldsm4(unsigned &r0, unsigned &r1, unsigned &r2, unsigned &r3,
                                      const __half* p) {
    unsigned a = (unsigned)__cvta_generic_to_shared(p);
    asm volatile("ldmatrix.sync.aligned.m8n8.x4.shared.b16 {%0,%1,%2,%3}, [%4];"
                 : "=r"(r0), "=r"(r1), "=r"(r2), "=r"(r3) : "r"(a));
}
__device__ __forceinline__ void ldsm4t(unsigned &r0, unsigned &r1, unsigned &r2, unsigned &r3,
                                       const __half* p) {
    unsigned a = (unsigned)__cvta_generic_to_shared(p);
    asm volatile("ldmatrix.sync.aligned.m8n8.x4.trans.shared.b16 {%0,%1,%2,%3}, [%4];"
                 : "=r"(r0), "=r"(r1), "=r"(r2), "=r"(r3) : "r"(a));
}

__device__ __forceinline__ unsigned ph2(float a, float b) {
    __half2 h = __floats2half2_rn(a, b);
    return *reinterpret_cast<unsigned*>(&h);
}

__device__ __forceinline__ void cpa16h(__half* smem_dst, const __half* gsrc) {
    unsigned s = (unsigned)__cvta_generic_to_shared(smem_dst);
    asm volatile("cp.async.cg.shared.global [%0], [%1], 16;" :: "r"(s), "l"(gsrc));
}
#define CP_COMMIT() asm volatile("cp.async.commit_group;")
#define CP_WAIT0()  asm volatile("cp.async.wait_group 0;")
#define PAIR_BAR(id) asm volatile("bar.sync %0, 64;" :: "r"((id) + 1) : "memory")

// ----------------------------------------------------------------------------
// QKV projection: tf32 MMA math (unchanged), fp16 output (scale folded into Q).
// ----------------------------------------------------------------------------
#define P_TM 128
#define P_TK 32
#define XSTR 36
#define WSTR 136
#define SOFT_SCALE 0.08838834764831845f   // 1/sqrt(128)

__global__ __launch_bounds__(256, 2)
void proj_kernel(const float* __restrict__ x,
                 const float* __restrict__ Wq,
                 const float* __restrict__ Wk,
                 const float* __restrict__ Wv)
{
    __shared__ float Xs[P_TM * XSTR];
    __shared__ float Wsm[P_TK * WSTR];

    const float* W   = (blockIdx.y == 0) ? Wq : (blockIdx.y == 1) ? Wk : Wv;
    __half*      out = (blockIdx.y == 0) ? g_q : (blockIdx.y == 1) ? g_k : g_v;
    const float  osc = (blockIdx.y == 0) ? SOFT_SCALE : 1.0f;

    const int row0 = blockIdx.x * P_TM;
    const int tid  = threadIdx.x, lane = tid & 31, w = tid >> 5;
    const int m0   = (w >> 1) * 32;
    const int half = w & 1;

    float4 xr[4], wr[4];
    const int xrr[4] = { (tid) >> 3, (tid + 256) >> 3, (tid + 512) >> 3, (tid + 768) >> 3 };
    const int xcc    = (tid & 7) * 4;
    const int wrr[4] = { (tid) >> 5, (tid + 256) >> 5, (tid + 512) >> 5, (tid + 768) >> 5 };
    const int wcc    = (tid & 31) * 4;

    auto load_regs = [&](int kt) {
#pragma unroll
        for (int it = 0; it < 4; it++)
            xr[it] = *(const float4*)&x[(size_t)(row0 + xrr[it]) * CC + kt + xcc];
#pragma unroll
        for (int it = 0; it < 4; it++)
            wr[it] = *(const float4*)&W[(size_t)(kt + wrr[it]) * HS + wcc];
    };
    auto store_smem = [&]() {
#pragma unroll
        for (int it = 0; it < 4; it++) {
            float4 v = xr[it];
            v.x = f2tff(v.x); v.y = f2tff(v.y); v.z = f2tff(v.z); v.w = f2tff(v.w);
            *(float4*)&Xs[xrr[it] * XSTR + xcc] = v;
        }
#pragma unroll
        for (int it = 0; it < 4; it++) {
            float4 v = wr[it];
            v.x = f2tff(v.x); v.y = f2tff(v.y); v.z = f2tff(v.z); v.w = f2tff(v.w);
            *(float4*)&Wsm[wrr[it] * WSTR + wcc] = v;
        }
    };

    float acc[2][8][4];
#pragma unroll
    for (int mf = 0; mf < 2; mf++)
#pragma unroll
        for (int f = 0; f < 8; f++)
#pragma unroll
            for (int r = 0; r < 4; r++) acc[mf][f][r] = 0.f;

    load_regs(0);
    for (int kt = 0; kt < CC; kt += P_TK) {
        store_smem();
        __syncthreads();
        if (kt + P_TK < CC) load_regs(kt + P_TK);

#pragma unroll
        for (int ks = 0; ks < 4; ks++) {
            const int k0 = ks * 8;
            unsigned a[2][4];
#pragma unroll
            for (int mf = 0; mf < 2; mf++) {
                int ar = m0 + mf * 16 + (lane >> 2);
                int ac = k0 + (lane & 3);
                a[mf][0] = __float_as_uint(Xs[ar * XSTR + ac]);
                a[mf][1] = __float_as_uint(Xs[(ar + 8) * XSTR + ac]);
                a[mf][2] = __float_as_uint(Xs[ar * XSTR + ac + 4]);
                a[mf][3] = __float_as_uint(Xs[(ar + 8) * XSTR + ac + 4]);
            }
#pragma unroll
            for (int f = 0; f < 8; f++) {
                int bc = half * 64 + f * 8 + (lane >> 2);
                unsigned b0 = __float_as_uint(Wsm[(k0 + (lane & 3)) * WSTR + bc]);
                unsigned b1 = __float_as_uint(Wsm[(k0 + 4 + (lane & 3)) * WSTR + bc]);
                mma8(acc[0][f], a[0][0], a[0][1], a[0][2], a[0][3], b0, b1);
                mma8(acc[1][f], a[1][0], a[1][1], a[1][2], a[1][3], b0, b1);
            }
        }
        __syncthreads();
    }

#pragma unroll
    for (int mf = 0; mf < 2; mf++) {
        int r = row0 + m0 + mf * 16 + (lane >> 2);
#pragma unroll
        for (int f = 0; f < 8; f++) {
            int c = half * 64 + f * 8 + 2 * (lane & 3);
            *(__half2*)&out[(size_t)r * HS + c] =
                __floats2half2_rn(acc[mf][f][0] * osc, acc[mf][f][1] * osc);
            *(__half2*)&out[(size_t)(r + 8) * HS + c] =
                __floats2half2_rn(acc[mf][f][2] * osc, acc[mf][f][3] * osc);
        }
    }
}

// ----------------------------------------------------------------------------
// Flash attention (causal), fp16 m16n8k16 + ldmatrix, fp32 accum/softmax.
// BM=BN=64, 256 threads. Balanced q-tile pair (qi, 63-qi), 65 iters/phase.
// Q fragments register-resident; own-half P fragments register-resident.
// ----------------------------------------------------------------------------
#define QSTRH 136   // halves; 272B row stride -> conflict-free ldmatrix
#define PSTRH 72    // 144B row stride

// smem layout (halves, then floats)
#define H_QS   0
#define H_KS   (H_QS + 64 * QSTRH)            // 2 buffers
#define H_VS   (H_KS + 2 * 64 * QSTRH)        // 2 buffers
#define H_PS   (H_VS + 2 * 64 * QSTRH)
#define H_TOT  (H_PS + 64 * PSTRH)
#define F_PMAX 0
#define F_PSUM 128
#define F_M    256
#define F_L    320
#define F_TOT  384
#define ATTN_SMEM_BYTES (H_TOT * 2 + F_TOT * 4)

__global__ __launch_bounds__(256, 1)
void attn_kernel(float* __restrict__ out)
{
    extern __shared__ char smraw[];
    __half* Qs  = (__half*)smraw;
    __half* Ksb = Qs + 64 * QSTRH;
    __half* Vsb = Ksb + 2 * 64 * QSTRH;
    __half* Ps  = Vsb + 2 * 64 * QSTRH;
    float*  fst = (float*)(smraw + H_TOT * 2);
    float* pmax = fst + F_PMAX;
    float* psum = fst + F_PSUM;
    float* m_sh = fst + F_M;
    float* l_sh = fst + F_L;

    const int tid = threadIdx.x, lane = tid & 31, w = tid >> 5;
    const int rg = w >> 1;      // pair id: rows rg*16..rg*16+15
    const int half = w & 1;     // column half
    const int b = blockIdx.y;

    const __half* qb = g_q + (size_t)b * TT * HS;
    const __half* kb = g_k + (size_t)b * TT * HS;
    const __half* vb = g_v + (size_t)b * TT * HS;

    const int r0 = rg * 16 + (lane >> 2);
    const int r1 = r0 + 8;

    // ldmatrix lane geometry
    const int lg = lane >> 3, lr = lane & 7;

    // cp.async chunk mapping: 64 rows x 128 halves = 1024 16B chunks, 4/thread
    for (int phase = 0; phase < 2; phase++) {
        const int qi = phase ? (63 - (int)blockIdx.x) : (int)blockIdx.x;
        __syncthreads();   // previous phase fully done with all smem

        // Prologue: async K/V (j=0) + Q loads
        {
            const __half* kg = kb;
            const __half* vg = vb;
            const __half* qg = qb + (size_t)qi * 64 * HS;
#pragma unroll
            for (int it = 0; it < 4; it++) {
                int ch = tid + it * 256;
                int r = ch >> 4, c = (ch & 15) * 8;
                cpa16h(&Ksb[r * QSTRH + c], &kg[(size_t)r * HS + c]);
                cpa16h(&Vsb[r * QSTRH + c], &vg[(size_t)r * HS + c]);
                cpa16h(&Qs [r * QSTRH + c], &qg[(size_t)r * HS + c]);
            }
            CP_COMMIT();
        }
        if (tid < 64) { m_sh[tid] = -1e30f; l_sh[tid] = 0.f; }

        CP_WAIT0();
        __syncthreads();

        // Q fragments -> registers (held for the whole phase). Scale pre-folded.
        unsigned qa[8][4];
        {
            const __half* qbase = &Qs[(rg * 16 + (lg & 1) * 8 + lr) * QSTRH + (lg >> 1) * 8];
#pragma unroll
            for (int ks = 0; ks < 8; ks++)
                ldsm4(qa[ks][0], qa[ks][1], qa[ks][2], qa[ks][3], qbase + ks * 16);
        }

        float o[8][4];
#pragma unroll
        for (int f = 0; f < 8; f++) { o[f][0] = o[f][1] = o[f][2] = o[f][3] = 0.f; }

        for (int j = 0; j <= qi; j++) {
            const int cur = j & 1;
            __half* Ks = Ksb + cur * 64 * QSTRH;
            __half* Vs = Vsb + cur * 64 * QSTRH;

            if (j > 0) { CP_WAIT0(); }
            __syncthreads();   // buf cur filled; prev iter done with Ps

            // Prefetch next K/V
            if (j < qi) {
                const __half* kg = kb + (size_t)(j + 1) * 64 * HS;
                const __half* vg = vb + (size_t)(j + 1) * 64 * HS;
                __half* Kn = Ksb + (1 - cur) * 64 * QSTRH;
                __half* Vn = Vsb + (1 - cur) * 64 * QSTRH;
#pragma unroll
                for (int it = 0; it < 4; it++) {
                    int ch = tid + it * 256;
                    int r = ch >> 4, c = (ch & 15) * 8;
                    cpa16h(&Kn[r * QSTRH + c], &kg[(size_t)r * HS + c]);
                    cpa16h(&Vn[r * QSTRH + c], &vg[(size_t)r * HS + c]);
                }
                CP_COMMIT();
            }

            // ---- S = Q K^T : warp = 16 rows x 32 cols, k=128 ----
            float s[4][4];
#pragma unroll
            for (int f = 0; f < 4; f++) { s[f][0] = s[f][1] = s[f][2] = s[f][3] = 0.f; }

            {
                // K B-frags: non-trans ldmatrix on [n][k] rows
                const __half* kbase = &Ks[(half * 32 + (lg >> 1) * 8 + lr) * QSTRH + (lg & 1) * 8];
#pragma unroll
                for (int ks = 0; ks < 8; ks++) {
#pragma unroll
                    for (int fp = 0; fp < 2; fp++) {
                        unsigned kb0, kb1, kb2, kb3;
                        ldsm4(kb0, kb1, kb2, kb3, kbase + fp * 16 * QSTRH + ks * 16);
                        mma16(s[fp * 2],     qa[ks][0], qa[ks][1], qa[ks][2], qa[ks][3], kb0, kb1);
                        mma16(s[fp * 2 + 1], qa[ks][0], qa[ks][1], qa[ks][2], qa[ks][3], kb2, kb3);
                    }
                }
            }

            // Causal mask (diagonal tile)
            if (j == qi) {
#pragma unroll
                for (int f = 0; f < 4; f++) {
                    int c = half * 32 + f * 8 + 2 * (lane & 3);
                    if (c     > r0) s[f][0] = -1e30f;
                    if (c + 1 > r0) s[f][1] = -1e30f;
                    if (c     > r1) s[f][2] = -1e30f;
                    if (c + 1 > r1) s[f][3] = -1e30f;
                }
            }

            // Row max (per half)
            float rm0 = -1e30f, rm1 = -1e30f;
#pragma unroll
            for (int f = 0; f < 4; f++) {
                rm0 = fmaxf(rm0, fmaxf(s[f][0], s[f][1]));
                rm1 = fmaxf(rm1, fmaxf(s[f][2], s[f][3]));
            }
            rm0 = fmaxf(rm0, __shfl_xor_sync(0xffffffffu, rm0, 1));
            rm0 = fmaxf(rm0, __shfl_xor_sync(0xffffffffu, rm0, 2));
            rm1 = fmaxf(rm1, __shfl_xor_sync(0xffffffffu, rm1, 1));
            rm1 = fmaxf(rm1, __shfl_xor_sync(0xffffffffu, rm1, 2));
            if ((lane & 3) == 0) {
                pmax[half * 64 + r0] = rm0;
                pmax[half * 64 + r1] = rm1;
            }
            PAIR_BAR(rg);

            // Online softmax; pack P to fp16 (own-half kept in regs + staged for partner)
            float mold0 = m_sh[r0], mold1 = m_sh[r1];
            float mn0 = fmaxf(mold0, fmaxf(pmax[r0], pmax[64 + r0]));
            float mn1 = fmaxf(mold1, fmaxf(pmax[r1], pmax[64 + r1]));
            float f0 = __expf(mold0 - mn0), f1 = __expf(mold1 - mn1);
            float sum0 = 0.f, sum1 = 0.f;
            unsigned own_a[2][4];
#pragma unroll
            for (int f = 0; f < 4; f++) {
                int c = half * 32 + f * 8 + 2 * (lane & 3);
                float p00 = __expf(s[f][0] - mn0), p01 = __expf(s[f][1] - mn0);
                float p10 = __expf(s[f][2] - mn1), p11 = __expf(s[f][3] - mn1);
                sum0 += p00 + p01; sum1 += p10 + p11;
                unsigned h2a = ph2(p00, p01);   // row r0
                unsigned h2b = ph2(p10, p11);   // row r1
                *(unsigned*)&Ps[r0 * PSTRH + c] = h2a;
                *(unsigned*)&Ps[r1 * PSTRH + c] = h2b;
                own_a[f >> 1][(f & 1) * 2]     = h2a;
                own_a[f >> 1][(f & 1) * 2 + 1] = h2b;
            }
            sum0 += __shfl_xor_sync(0xffffffffu, sum0, 1);
            sum0 += __shfl_xor_sync(0xffffffffu, sum0, 2);
            sum1 += __shfl_xor_sync(0xffffffffu, sum1, 1);
            sum1 += __shfl_xor_sync(0xffffffffu, sum1, 2);
            if ((lane & 3) == 0) {
                psum[half * 64 + r0] = sum0;
                psum[half * 64 + r1] = sum1;
            }

            // Rescale O accumulators
#pragma unroll
            for (int f = 0; f < 8; f++) {
                o[f][0] *= f0; o[f][1] *= f0; o[f][2] *= f1; o[f][3] *= f1;
            }
            PAIR_BAR(rg);

            // Row stats update (pair-local)
            if (half == 0 && (lane & 3) == 0) {
#pragma unroll
                for (int rr = 0; rr < 2; rr++) {
                    int r = rr ? r1 : r0;
                    float mo = m_sh[r];
                    float mn = fmaxf(mo, fmaxf(pmax[r], pmax[64 + r]));
                    l_sh[r] = l_sh[r] * __expf(mo - mn) + psum[r] + psum[64 + r];
                    m_sh[r] = mn;
                }
            }

            // ---- O += P V : warp = 16 rows x 64 hs-cols, k=64 ----
            {
                const __half* vbase = &Vs[((lg & 1) * 8 + lr) * QSTRH + half * 64 + (lg >> 1) * 8];
                const __half* pbase = &Ps[(rg * 16 + (lg & 1) * 8 + lr) * PSTRH + (lg >> 1) * 8];
#pragma unroll
                for (int gs = 0; gs < 4; gs++) {
                    unsigned a0, a1, a2, a3;
                    if ((gs >> 1) == half) {
                        int loc = gs & 1;
                        a0 = own_a[loc][0]; a1 = own_a[loc][1];
                        a2 = own_a[loc][2]; a3 = own_a[loc][3];
                    } else {
                        ldsm4(a0, a1, a2, a3, pbase + gs * 16);
                    }
#pragma unroll
                    for (int np = 0; np < 4; np++) {
                        unsigned vb0, vb1, vb2, vb3;
                        ldsm4t(vb0, vb1, vb2, vb3, vbase + gs * 16 * QSTRH + np * 16);
                        mma16(o[np * 2],     a0, a1, a2, a3, vb0, vb1);
                        mma16(o[np * 2 + 1], a0, a1, a2, a3, vb2, vb3);
                    }
                }
            }
        }

        // Normalize and store
        PAIR_BAR(rg);
        float li0 = 1.f / l_sh[r0];
        float li1 = 1.f / l_sh[r1];
        float* ob = out + ((size_t)b * TT + (size_t)qi * 64) * HS;
#pragma unroll
        for (int f = 0; f < 8; f++) {
            int c = half * 64 + f * 8 + 2 * (lane & 3);
            *(float2*)&ob[(size_t)r0 * HS + c] = make_float2(o[f][0] * li0, o[f][1] * li0);
            *(float2*)&ob[(size_t)r1 * HS + c] = make_float2(o[f][2] * li1, o[f][3] * li1);
        }
    }
}

// ----------------------------------------------------------------------------
// Launcher
// ----------------------------------------------------------------------------
extern "C" void kernel_launch(void* const* d_in, const int* in_sizes, int n_in,
                              void* d_out, int out_size)
{
    const float* x  = (const float*)d_in[0];
    const float* Wq = (const float*)d_in[1];
    const float* Wk = (const float*)d_in[2];
    const float* Wv = (const float*)d_in[3];
    float* out = (float*)d_out;

    dim3 pg(MM / P_TM, 3);
    proj_kernel<<<pg, 256>>>(x, Wq, Wk, Wv);

    cudaFuncSetAttribute(attn_kernel,
                         cudaFuncAttributeMaxDynamicSharedMemorySize,
                         ATTN_SMEM_BYTES);
    dim3 ag(32, BB);
    attn_kernel<<<ag, 256, ATTN_SMEM_BYTES>>>(out);
}

// round 9
// speedup vs baseline: 8.9682x; 1.0295x over previous
#include <cuda_runtime.h>
#include <cuda_fp16.h>
#include <math.h>

// Problem constants
#define BB 4
#define TT 4096
#define CC 1024
#define HS 128
#define MM (BB * TT)

// ----------------------------------------------------------------------------
// Scratch (device globals). fp16 q/k/v. q pre-scaled by log2(e)/sqrt(HS).
// ----------------------------------------------------------------------------
__device__ __half g_q[MM * HS];
__device__ __half g_k[MM * HS];
__device__ __half g_v[MM * HS];

// ----------------------------------------------------------------------------
// helpers
// ----------------------------------------------------------------------------
__device__ __forceinline__ void mma16(float c[4],
                                      unsigned a0, unsigned a1, unsigned a2, unsigned a3,
                                      unsigned b0, unsigned b1) {
    asm volatile(
        "mma.sync.aligned.m16n8k16.row.col.f32.f16.f16.f32 "
        "{%0,%1,%2,%3},{%4,%5,%6,%7},{%8,%9},{%0,%1,%2,%3};"
        : "+f"(c[0]), "+f"(c[1]), "+f"(c[2]), "+f"(c[3])
        : "r"(a0), "r"(a1), "r"(a2), "r"(a3), "r"(b0), "r"(b1));
}
__device__ __forceinline__ void ldsm4(unsigned &r0, unsigned &r1, unsigned &r2, unsigned &r3,
                                      const __half* p) {
    unsigned a = (unsigned)__cvta_generic_to_shared(p);
    asm volatile("ldmatrix.sync.aligned.m8n8.x4.shared.b16 {%0,%1,%2,%3}, [%4];"
                 : "=r"(r0), "=r"(r1), "=r"(r2), "=r"(r3) : "r"(a));
}
__device__ __forceinline__ void ldsm4t(unsigned &r0, unsigned &r1, unsigned &r2, unsigned &r3,
                                       const __half* p) {
    unsigned a = (unsigned)__cvta_generic_to_shared(p);
    asm volatile("ldmatrix.sync.aligned.m8n8.x4.trans.shared.b16 {%0,%1,%2,%3}, [%4];"
                 : "=r"(r0), "=r"(r1), "=r"(r2), "=r"(r3) : "r"(a));
}
__device__ __forceinline__ unsigned ph2(float a, float b) {
    __half2 h = __floats2half2_rn(a, b);
    return *reinterpret_cast<unsigned*>(&h);
}
__device__ __forceinline__ float fexp2(float x) {
    float y; asm("ex2.approx.f32 %0, %1;" : "=f"(y) : "f"(x)); return y;
}
__device__ __forceinline__ void cpa16h(__half* smem_dst, const __half* gsrc) {
    unsigned s = (unsigned)__cvta_generic_to_shared(smem_dst);
    asm volatile("cp.async.cg.shared.global [%0], [%1], 16;" :: "r"(s), "l"(gsrc));
}
#define CP_COMMIT() asm volatile("cp.async.commit_group;")
#define CP_WAIT0()  asm volatile("cp.async.wait_group 0;")
#define PAIR_BAR(id) asm volatile("bar.sync %0, 64;" :: "r"((id) + 1) : "memory")

// Q pre-scale: (1/sqrt(128)) * log2(e)  -> softmax uses ex2 directly
#define Q_SCALE 0.1275310250309574f

// ----------------------------------------------------------------------------
// QKV projection, fp16 MMA (m16n8k16) + ldmatrix, fp32 accum.
// Tile 128x128, K-tile 32. 8 warps: warp = m32 x n64.
// ----------------------------------------------------------------------------
#define P_TK 32
#define XSTRH 72    // 144B row stride: 144/16=9 == 1 mod 8 -> conflict-free ldsm
#define WSTRH 136   // 272B: 17 == 1 mod 8

__global__ __launch_bounds__(256, 2)
void proj_kernel(const float* __restrict__ x,
                 const float* __restrict__ Wq,
                 const float* __restrict__ Wk,
                 const float* __restrict__ Wv)
{
    __shared__ __half Xh[128 * XSTRH];
    __shared__ __half Wh[P_TK * WSTRH];

    const float* W   = (blockIdx.y == 0) ? Wq : (blockIdx.y == 1) ? Wk : Wv;
    __half*      out = (blockIdx.y == 0) ? g_q : (blockIdx.y == 1) ? g_k : g_v;
    const float  osc = (blockIdx.y == 0) ? Q_SCALE : 1.0f;

    const int row0 = blockIdx.x * 128;
    const int tid  = threadIdx.x, lane = tid & 31, w = tid >> 5;
    const int m0   = (w >> 1) * 32;
    const int half = w & 1;
    const int lg = lane >> 3, lr = lane & 7;

    float4 xr[4], wr[4];
    const int xrr[4] = { (tid) >> 3, (tid + 256) >> 3, (tid + 512) >> 3, (tid + 768) >> 3 };
    const int xcc    = (tid & 7) * 4;
    const int wrr[4] = { (tid) >> 5, (tid + 256) >> 5, (tid + 512) >> 5, (tid + 768) >> 5 };
    const int wcc    = (tid & 31) * 4;

    auto load_regs = [&](int kt) {
#pragma unroll
        for (int it = 0; it < 4; it++)
            xr[it] = *(const float4*)&x[(size_t)(row0 + xrr[it]) * CC + kt + xcc];
#pragma unroll
        for (int it = 0; it < 4; it++)
            wr[it] = *(const float4*)&W[(size_t)(kt + wrr[it]) * HS + wcc];
    };
    auto store_smem = [&]() {
#pragma unroll
        for (int it = 0; it < 4; it++) {
            float4 v = xr[it];
            unsigned h0 = ph2(v.x, v.y), h1 = ph2(v.z, v.w);
            *(uint2*)&Xh[xrr[it] * XSTRH + xcc] = make_uint2(h0, h1);
        }
#pragma unroll
        for (int it = 0; it < 4; it++) {
            float4 v = wr[it];
            unsigned h0 = ph2(v.x, v.y), h1 = ph2(v.z, v.w);
            *(uint2*)&Wh[wrr[it] * WSTRH + wcc] = make_uint2(h0, h1);
        }
    };

    float acc[2][16][4];
#pragma unroll
    for (int mf = 0; mf < 2; mf++)
#pragma unroll
        for (int f = 0; f < 16; f++)
#pragma unroll
            for (int r = 0; r < 4; r++) acc[mf][f][r] = 0.f;
    // note: only 8 n-frags used per warp (n64); declare 8
    // (kept 16 above would waste regs) -- use 8:
    // (redeclared below properly)

    // proper accumulators: 2 m-frags x 8 n-frags
    float ac[2][8][4];
#pragma unroll
    for (int mf = 0; mf < 2; mf++)
#pragma unroll
        for (int f = 0; f < 8; f++)
#pragma unroll
            for (int r = 0; r < 4; r++) ac[mf][f][r] = 0.f;

    load_regs(0);
    for (int kt = 0; kt < CC; kt += P_TK) {
        store_smem();
        __syncthreads();
        if (kt + P_TK < CC) load_regs(kt + P_TK);

#pragma unroll
        for (int kg = 0; kg < 2; kg++) {
            unsigned a[2][4];
#pragma unroll
            for (int mf = 0; mf < 2; mf++)
                ldsm4(a[mf][0], a[mf][1], a[mf][2], a[mf][3],
                      &Xh[(m0 + mf * 16 + (lg & 1) * 8 + lr) * XSTRH + kg * 16 + (lg >> 1) * 8]);
#pragma unroll
            for (int np = 0; np < 4; np++) {
                unsigned b0, b1, b2, b3;
                ldsm4t(b0, b1, b2, b3,
                       &Wh[(kg * 16 + (lg & 1) * 8 + lr) * WSTRH + half * 64 + np * 16 + (lg >> 1) * 8]);
#pragma unroll
                for (int mf = 0; mf < 2; mf++) {
                    mma16(ac[mf][np * 2],     a[mf][0], a[mf][1], a[mf][2], a[mf][3], b0, b1);
                    mma16(ac[mf][np * 2 + 1], a[mf][0], a[mf][1], a[mf][2], a[mf][3], b2, b3);
                }
            }
        }
        __syncthreads();
    }

#pragma unroll
    for (int mf = 0; mf < 2; mf++) {
        int r = row0 + m0 + mf * 16 + (lane >> 2);
#pragma unroll
        for (int f = 0; f < 8; f++) {
            int c = half * 64 + f * 8 + 2 * (lane & 3);
            *(__half2*)&out[(size_t)r * HS + c] =
                __floats2half2_rn(ac[mf][f][0] * osc, ac[mf][f][1] * osc);
            *(__half2*)&out[(size_t)(r + 8) * HS + c] =
                __floats2half2_rn(ac[mf][f][2] * osc, ac[mf][f][3] * osc);
        }
    }
}

// ----------------------------------------------------------------------------
// Flash attention (causal), fp16 MMA, fp32 accum/softmax.
// BM=BN=64. Pair (qi,63-qi) phases. Warp = 16 rows x 32 s-cols (own half).
// PV split-K: warp keeps partial O (16x128) over its own 32 s-cols in regs;
// pair-reduce once per phase. m/l in registers; 1 pair-bar + 1 ctasync per iter.
// ----------------------------------------------------------------------------
#define QSTRH 136

#define H_QS   0
#define H_KS   (H_QS + 64 * QSTRH)
#define H_VS   (H_KS + 2 * 64 * QSTRH)
#define H_TOT  (H_VS + 2 * 64 * QSTRH)
#define ATTN_SMEM_BYTES (H_TOT * 2 + 256 * 4)

__global__ __launch_bounds__(256, 1)
void attn_kernel(float* __restrict__ out)
{
    extern __shared__ char smraw[];
    __half* Qs  = (__half*)smraw;
    __half* Ksb = Qs + 64 * QSTRH;
    __half* Vsb = Ksb + 2 * 64 * QSTRH;
    float*  fst = (float*)(smraw + H_TOT * 2);
    float* pmax = fst;          // [128]
    float* lx   = fst + 128;    // [128]
    float* scratch = (float*)Ksb;   // 8192 floats, used only at phase end

    const int tid = threadIdx.x, lane = tid & 31, w = tid >> 5;
    const int rg = w >> 1;
    const int half = w & 1;
    const int b = blockIdx.y;

    const __half* qb = g_q + (size_t)b * TT * HS;
    const __half* kb = g_k + (size_t)b * TT * HS;
    const __half* vb = g_v + (size_t)b * TT * HS;

    const int r0 = rg * 16 + (lane >> 2);
    const int r1 = r0 + 8;
    const int r0l = lane >> 2;            // local row 0..7
    const int lg = lane >> 3, lr = lane & 7;

    for (int phase = 0; phase < 2; phase++) {
        const int qi = phase ? (63 - (int)blockIdx.x) : (int)blockIdx.x;
        __syncthreads();   // previous phase done with ALL smem (incl. scratch)

        // Prologue: async K/V (j=0) + Q
        {
            const __half* kg = kb;
            const __half* vg = vb;
            const __half* qg = qb + (size_t)qi * 64 * HS;
#pragma unroll
            for (int it = 0; it < 4; it++) {
                int ch = tid + it * 256;
                int r = ch >> 4, c = (ch & 15) * 8;
                cpa16h(&Ksb[r * QSTRH + c], &kg[(size_t)r * HS + c]);
                cpa16h(&Vsb[r * QSTRH + c], &vg[(size_t)r * HS + c]);
                cpa16h(&Qs [r * QSTRH + c], &qg[(size_t)r * HS + c]);
            }
            CP_COMMIT();
        }

        float m0r = -1e30f, m1r = -1e30f, l0r = 0.f, l1r = 0.f;

        CP_WAIT0();
        __syncthreads();

        // Q fragments -> registers (whole phase). Scale+log2e pre-folded.
        unsigned qa[8][4];
        {
            const __half* qbase = &Qs[(rg * 16 + (lg & 1) * 8 + lr) * QSTRH + (lg >> 1) * 8];
#pragma unroll
            for (int ks = 0; ks < 8; ks++)
                ldsm4(qa[ks][0], qa[ks][1], qa[ks][2], qa[ks][3], qbase + ks * 16);
        }

        // Partial O: 16 rows x 128 hs (own 32 s-cols only)
        float o[16][4];
#pragma unroll
        for (int f = 0; f < 16; f++) { o[f][0] = o[f][1] = o[f][2] = o[f][3] = 0.f; }

        for (int j = 0; j <= qi; j++) {
            const int cur = j & 1;
            __half* Ks = Ksb + cur * 64 * QSTRH;
            __half* Vs = Vsb + cur * 64 * QSTRH;

            CP_WAIT0();
            __syncthreads();

            if (j < qi) {
                const __half* kg = kb + (size_t)(j + 1) * 64 * HS;
                const __half* vg = vb + (size_t)(j + 1) * 64 * HS;
                __half* Kn = Ksb + (1 - cur) * 64 * QSTRH;
                __half* Vn = Vsb + (1 - cur) * 64 * QSTRH;
#pragma unroll
                for (int it = 0; it < 4; it++) {
                    int ch = tid + it * 256;
                    int r = ch >> 4, c = (ch & 15) * 8;
                    cpa16h(&Kn[r * QSTRH + c], &kg[(size_t)r * HS + c]);
                    cpa16h(&Vn[r * QSTRH + c], &vg[(size_t)r * HS + c]);
                }
                CP_COMMIT();
            }

            // ---- S = Q K^T : 16 rows x 32 cols (own half), k=128 ----
            float s[4][4];
#pragma unroll
            for (int f = 0; f < 4; f++) { s[f][0] = s[f][1] = s[f][2] = s[f][3] = 0.f; }
            {
                const __half* kbase = &Ks[(half * 32 + (lg >> 1) * 8 + lr) * QSTRH + (lg & 1) * 8];
#pragma unroll
                for (int ks = 0; ks < 8; ks++) {
#pragma unroll
                    for (int fp = 0; fp < 2; fp++) {
                        unsigned kb0, kb1, kb2, kb3;
                        ldsm4(kb0, kb1, kb2, kb3, kbase + fp * 16 * QSTRH + ks * 16);
                        mma16(s[fp * 2],     qa[ks][0], qa[ks][1], qa[ks][2], qa[ks][3], kb0, kb1);
                        mma16(s[fp * 2 + 1], qa[ks][0], qa[ks][1], qa[ks][2], qa[ks][3], kb2, kb3);
                    }
                }
            }

            // Causal mask (diagonal tile)
            if (j == qi) {
#pragma unroll
                for (int f = 0; f < 4; f++) {
                    int c = half * 32 + f * 8 + 2 * (lane & 3);
                    if (c     > r0) s[f][0] = -1e30f;
                    if (c + 1 > r0) s[f][1] = -1e30f;
                    if (c     > r1) s[f][2] = -1e30f;
                    if (c + 1 > r1) s[f][3] = -1e30f;
                }
            }

            // Row max over own half, exchange with partner
            float rm0 = -1e30f, rm1 = -1e30f;
#pragma unroll
            for (int f = 0; f < 4; f++) {
                rm0 = fmaxf(rm0, fmaxf(s[f][0], s[f][1]));
                rm1 = fmaxf(rm1, fmaxf(s[f][2], s[f][3]));
            }
            rm0 = fmaxf(rm0, __shfl_xor_sync(0xffffffffu, rm0, 1));
            rm0 = fmaxf(rm0, __shfl_xor_sync(0xffffffffu, rm0, 2));
            rm1 = fmaxf(rm1, __shfl_xor_sync(0xffffffffu, rm1, 1));
            rm1 = fmaxf(rm1, __shfl_xor_sync(0xffffffffu, rm1, 2));
            if ((lane & 3) == 0) {
                pmax[half * 64 + r0] = rm0;
                pmax[half * 64 + r1] = rm1;
            }
            PAIR_BAR(rg);

            // Softmax (registers; shared m sequence across the pair)
            float mn0 = fmaxf(m0r, fmaxf(pmax[r0], pmax[64 + r0]));
            float mn1 = fmaxf(m1r, fmaxf(pmax[r1], pmax[64 + r1]));
            float f0 = fexp2(m0r - mn0), f1 = fexp2(m1r - mn1);
            float sum0 = 0.f, sum1 = 0.f;
            unsigned own_a[2][4];
#pragma unroll
            for (int f = 0; f < 4; f++) {
                float p00 = fexp2(s[f][0] - mn0), p01 = fexp2(s[f][1] - mn0);
                float p10 = fexp2(s[f][2] - mn1), p11 = fexp2(s[f][3] - mn1);
                sum0 += p00 + p01; sum1 += p10 + p11;
                own_a[f >> 1][(f & 1) * 2]     = ph2(p00, p01);
                own_a[f >> 1][(f & 1) * 2 + 1] = ph2(p10, p11);
            }
            sum0 += __shfl_xor_sync(0xffffffffu, sum0, 1);
            sum0 += __shfl_xor_sync(0xffffffffu, sum0, 2);
            sum1 += __shfl_xor_sync(0xffffffffu, sum1, 1);
            sum1 += __shfl_xor_sync(0xffffffffu, sum1, 2);
            l0r = l0r * f0 + sum0;  m0r = mn0;
            l1r = l1r * f1 + sum1;  m1r = mn1;

            // Rescale partial O
#pragma unroll
            for (int f = 0; f < 16; f++) {
                o[f][0] *= f0; o[f][1] *= f0; o[f][2] *= f1; o[f][3] *= f1;
            }

            // ---- partial O += P_own V_own : k = own 32 s-cols, n = 128 hs ----
            {
#pragma unroll
                for (int kg = 0; kg < 2; kg++) {
                    const __half* vbase =
                        &Vs[(half * 32 + kg * 16 + (lg & 1) * 8 + lr) * QSTRH + (lg >> 1) * 8];
#pragma unroll
                    for (int np = 0; np < 8; np++) {
                        unsigned vb0, vb1, vb2, vb3;
                        ldsm4t(vb0, vb1, vb2, vb3, vbase + np * 16);
                        mma16(o[np * 2],     own_a[kg][0], own_a[kg][1], own_a[kg][2], own_a[kg][3], vb0, vb1);
                        mma16(o[np * 2 + 1], own_a[kg][0], own_a[kg][1], own_a[kg][2], own_a[kg][3], vb2, vb3);
                    }
                }
            }
        }

        // ---- Phase end: pair-reduce partial O (once), then store ----
        __syncthreads();   // all warps done reading Ks/Vs (scratch aliases Ksb)

        // write partner's hs-half partial + own l
        {
            float* wr = scratch + (rg * 2 + half) * 1024;
#pragma unroll
            for (int i = 0; i < 8; i++) {
                int nf = (1 - half) * 8 + i;
                int cl = i * 8 + 2 * (lane & 3);
                *(float2*)&wr[r0l * 64 + cl]       = make_float2(o[nf][0], o[nf][1]);
                *(float2*)&wr[(r0l + 8) * 64 + cl] = make_float2(o[nf][2], o[nf][3]);
            }
            if ((lane & 3) == 0) {
                lx[half * 64 + r0] = l0r;
                lx[half * 64 + r1] = l1r;
            }
        }
        PAIR_BAR(rg);

        float lt0 = lx[r0] + lx[64 + r0];
        float lt1 = lx[r1] + lx[64 + r1];
        float li0 = 1.f / lt0, li1 = 1.f / lt1;

        {
            const float* pr = scratch + (rg * 2 + (1 - half)) * 1024;
            float* ob = out + ((size_t)b * TT + (size_t)qi * 64) * HS;
#pragma unroll
            for (int i = 0; i < 8; i++) {
                int nf = half * 8 + i;
                int cl = i * 8 + 2 * (lane & 3);
                float2 pa = *(const float2*)&pr[r0l * 64 + cl];
                float2 pb = *(const float2*)&pr[(r0l + 8) * 64 + cl];
                int c = half * 64 + cl;
                *(float2*)&ob[(size_t)r0 * HS + c] =
                    make_float2((o[nf][0] + pa.x) * li0, (o[nf][1] + pa.y) * li0);
                *(float2*)&ob[(size_t)r1 * HS + c] =
                    make_float2((o[nf][2] + pb.x) * li1, (o[nf][3] + pb.y) * li1);
            }
        }
    }
}

// ----------------------------------------------------------------------------
// Launcher
// ----------------------------------------------------------------------------
extern "C" void kernel_launch(void* const* d_in, const int* in_sizes, int n_in,
                              void* d_out, int out_size)
{
    const float* x  = (const float*)d_in[0];
    const float* Wq = (const float*)d_in[1];
    const float* Wk = (const float*)d_in[2];
    const float* Wv = (const float*)d_in[3];
    float* out = (float*)d_out;

    dim3 pg(MM / 128, 3);
    proj_kernel<<<pg, 256>>>(x, Wq, Wk, Wv);

    cudaFuncSetAttribute(attn_kernel,
                         cudaFuncAttributeMaxDynamicSharedMemorySize,
                         ATTN_SMEM_BYTES);
    dim3 ag(32, BB);
    attn_kernel<<<ag, 256, ATTN_SMEM_BYTES>>>(out);
}

// round 11
// speedup vs baseline: 11.6042x; 1.2939x over previous
#include <cuda_runtime.h>
#include <cuda_fp16.h>
#include <math.h>

// Problem constants
#define BB 4
#define TT 4096
#define CC 1024
#define HS 128
#define MM (BB * TT)

// ----------------------------------------------------------------------------
// Scratch (device globals). fp16 q/k/v. q pre-scaled by log2(e)/sqrt(HS).
// ----------------------------------------------------------------------------
__device__ __half g_q[MM * HS];
__device__ __half g_k[MM * HS];
__device__ __half g_v[MM * HS];

// ----------------------------------------------------------------------------
// helpers
// ----------------------------------------------------------------------------
__device__ __forceinline__ void mma16(float c[4],
                                      unsigned a0, unsigned a1, unsigned a2, unsigned a3,
                                      unsigned b0, unsigned b1) {
    asm volatile(
        "mma.sync.aligned.m16n8k16.row.col.f32.f16.f16.f32 "
        "{%0,%1,%2,%3},{%4,%5,%6,%7},{%8,%9},{%0,%1,%2,%3};"
        : "+f"(c[0]), "+f"(c[1]), "+f"(c[2]), "+f"(c[3])
        : "r"(a0), "r"(a1), "r"(a2), "r"(a3), "r"(b0), "r"(b1));
}
__device__ __forceinline__ void ldsm4(unsigned &r0, unsigned &r1, unsigned &r2, unsigned &r3,
                                      const __half* p) {
    unsigned a = (unsigned)__cvta_generic_to_shared(p);
    asm volatile("ldmatrix.sync.aligned.m8n8.x4.shared.b16 {%0,%1,%2,%3}, [%4];"
                 : "=r"(r0), "=r"(r1), "=r"(r2), "=r"(r3) : "r"(a));
}
__device__ __forceinline__ void ldsm4t(unsigned &r0, unsigned &r1, unsigned &r2, unsigned &r3,
                                       const __half* p) {
    unsigned a = (unsigned)__cvta_generic_to_shared(p);
    asm volatile("ldmatrix.sync.aligned.m8n8.x4.trans.shared.b16 {%0,%1,%2,%3}, [%4];"
                 : "=r"(r0), "=r"(r1), "=r"(r2), "=r"(r3) : "r"(a));
}
__device__ __forceinline__ unsigned ph2(float a, float b) {
    __half2 h = __floats2half2_rn(a, b);
    return *reinterpret_cast<unsigned*>(&h);
}
__device__ __forceinline__ float fexp2(float x) {
    float y; asm("ex2.approx.f32 %0, %1;" : "=f"(y) : "f"(x)); return y;
}
__device__ __forceinline__ void cpa16h(__half* smem_dst, const __half* gsrc) {
    unsigned s = (unsigned)__cvta_generic_to_shared(smem_dst);
    asm volatile("cp.async.cg.shared.global [%0], [%1], 16;" :: "r"(s), "l"(gsrc));
}
#define CP_COMMIT() asm volatile("cp.async.commit_group;")
#define CP_WAIT0()  asm volatile("cp.async.wait_group 0;")
#define PAIR_BAR(id) asm volatile("bar.sync %0, 64;" :: "r"((id) + 1) : "memory")

// Q pre-scale: (1/sqrt(128)) * log2(e)  -> softmax uses ex2 directly
#define Q_SCALE 0.1275310250309574f

// ----------------------------------------------------------------------------
// QKV projection, fp16 MMA (m16n8k16) + ldmatrix, fp32 accum.  (R9, measured ~63us)
// Tile 128x128, K-tile 32. 8 warps: warp = m32 x n64.
// ----------------------------------------------------------------------------
#define P_TK 32
#define XSTRH 72    // 144B row stride -> conflict-free ldsm
#define WSTRH 136   // 272B row stride

__global__ __launch_bounds__(256, 2)
void proj_kernel(const float* __restrict__ x,
                 const float* __restrict__ Wq,
                 const float* __restrict__ Wk,
                 const float* __restrict__ Wv)
{
    __shared__ __half Xh[128 * XSTRH];
    __shared__ __half Wh[P_TK * WSTRH];

    const float* W   = (blockIdx.y == 0) ? Wq : (blockIdx.y == 1) ? Wk : Wv;
    __half*      out = (blockIdx.y == 0) ? g_q : (blockIdx.y == 1) ? g_k : g_v;
    const float  osc = (blockIdx.y == 0) ? Q_SCALE : 1.0f;

    const int row0 = blockIdx.x * 128;
    const int tid  = threadIdx.x, lane = tid & 31, w = tid >> 5;
    const int m0   = (w >> 1) * 32;
    const int half = w & 1;
    const int lg = lane >> 3, lr = lane & 7;

    float4 xr[4], wr[4];
    const int xrr[4] = { (tid) >> 3, (tid + 256) >> 3, (tid + 512) >> 3, (tid + 768) >> 3 };
    const int xcc    = (tid & 7) * 4;
    const int wrr[4] = { (tid) >> 5, (tid + 256) >> 5, (tid + 512) >> 5, (tid + 768) >> 5 };
    const int wcc    = (tid & 31) * 4;

    auto load_regs = [&](int kt) {
#pragma unroll
        for (int it = 0; it < 4; it++)
            xr[it] = *(const float4*)&x[(size_t)(row0 + xrr[it]) * CC + kt + xcc];
#pragma unroll
        for (int it = 0; it < 4; it++)
            wr[it] = *(const float4*)&W[(size_t)(kt + wrr[it]) * HS + wcc];
    };
    auto store_smem = [&]() {
#pragma unroll
        for (int it = 0; it < 4; it++) {
            float4 v = xr[it];
            *(uint2*)&Xh[xrr[it] * XSTRH + xcc] = make_uint2(ph2(v.x, v.y), ph2(v.z, v.w));
        }
#pragma unroll
        for (int it = 0; it < 4; it++) {
            float4 v = wr[it];
            *(uint2*)&Wh[wrr[it] * WSTRH + wcc] = make_uint2(ph2(v.x, v.y), ph2(v.z, v.w));
        }
    };

    float ac[2][8][4];
#pragma unroll
    for (int mf = 0; mf < 2; mf++)
#pragma unroll
        for (int f = 0; f < 8; f++)
#pragma unroll
            for (int r = 0; r < 4; r++) ac[mf][f][r] = 0.f;

    load_regs(0);
    for (int kt = 0; kt < CC; kt += P_TK) {
        store_smem();
        __syncthreads();
        if (kt + P_TK < CC) load_regs(kt + P_TK);

#pragma unroll
        for (int kg = 0; kg < 2; kg++) {
            unsigned a[2][4];
#pragma unroll
            for (int mf = 0; mf < 2; mf++)
                ldsm4(a[mf][0], a[mf][1], a[mf][2], a[mf][3],
                      &Xh[(m0 + mf * 16 + (lg & 1) * 8 + lr) * XSTRH + kg * 16 + (lg >> 1) * 8]);
#pragma unroll
            for (int np = 0; np < 4; np++) {
                unsigned b0, b1, b2, b3;
                ldsm4t(b0, b1, b2, b3,
                       &Wh[(kg * 16 + (lg & 1) * 8 + lr) * WSTRH + half * 64 + np * 16 + (lg >> 1) * 8]);
#pragma unroll
                for (int mf = 0; mf < 2; mf++) {
                    mma16(ac[mf][np * 2],     a[mf][0], a[mf][1], a[mf][2], a[mf][3], b0, b1);
                    mma16(ac[mf][np * 2 + 1], a[mf][0], a[mf][1], a[mf][2], a[mf][3], b2, b3);
                }
            }
        }
        __syncthreads();
    }

#pragma unroll
    for (int mf = 0; mf < 2; mf++) {
        int r = row0 + m0 + mf * 16 + (lane >> 2);
#pragma unroll
        for (int f = 0; f < 8; f++) {
            int c = half * 64 + f * 8 + 2 * (lane & 3);
            *(__half2*)&out[(size_t)r * HS + c] =
                __floats2half2_rn(ac[mf][f][0] * osc, ac[mf][f][1] * osc);
            *(__half2*)&out[(size_t)(r + 8) * HS + c] =
                __floats2half2_rn(ac[mf][f][2] * osc, ac[mf][f][3] * osc);
        }
    }
}

// ----------------------------------------------------------------------------
// Flash attention (R8 structure, measured 98.5us; + ex2 softmax).
// BM=BN=64, 256 threads. Balanced pair (qi, 63-qi). Q frags register-resident;
// own-half P frags register-resident, partner half via smem ldmatrix.
// ----------------------------------------------------------------------------
#define QSTRH 136
#define PSTRH 72

#define H_QS   0
#define H_KS   (H_QS + 64 * QSTRH)
#define H_VS   (H_KS + 2 * 64 * QSTRH)
#define H_PS   (H_VS + 2 * 64 * QSTRH)
#define H_TOT  (H_PS + 64 * PSTRH)
#define F_PMAX 0
#define F_PSUM 128
#define F_M    256
#define F_L    320
#define F_TOT  384
#define ATTN_SMEM_BYTES (H_TOT * 2 + F_TOT * 4)

__global__ __launch_bounds__(256, 1)
void attn_kernel(float* __restrict__ out)
{
    extern __shared__ char smraw[];
    __half* Qs  = (__half*)smraw;
    __half* Ksb = Qs + 64 * QSTRH;
    __half* Vsb = Ksb + 2 * 64 * QSTRH;
    __half* Ps  = Vsb + 2 * 64 * QSTRH;
    float*  fst = (float*)(smraw + H_TOT * 2);
    float* pmax = fst + F_PMAX;
    float* psum = fst + F_PSUM;
    float* m_sh = fst + F_M;
    float* l_sh = fst + F_L;

    const int tid = threadIdx.x, lane = tid & 31, w = tid >> 5;
    const int rg = w >> 1;
    const int half = w & 1;
    const int b = blockIdx.y;

    const __half* qb = g_q + (size_t)b * TT * HS;
    const __half* kb = g_k + (size_t)b * TT * HS;
    const __half* vb = g_v + (size_t)b * TT * HS;

    const int r0 = rg * 16 + (lane >> 2);
    const int r1 = r0 + 8;
    const int lg = lane >> 3, lr = lane & 7;

    for (int phase = 0; phase < 2; phase++) {
        const int qi = phase ? (63 - (int)blockIdx.x) : (int)blockIdx.x;
        __syncthreads();

        // Prologue: async K/V (j=0) + Q
        {
            const __half* kg = kb;
            const __half* vg = vb;
            const __half* qg = qb + (size_t)qi * 64 * HS;
#pragma unroll
            for (int it = 0; it < 4; it++) {
                int ch = tid + it * 256;
                int r = ch >> 4, c = (ch & 15) * 8;
                cpa16h(&Ksb[r * QSTRH + c], &kg[(size_t)r * HS + c]);
                cpa16h(&Vsb[r * QSTRH + c], &vg[(size_t)r * HS + c]);
                cpa16h(&Qs [r * QSTRH + c], &qg[(size_t)r * HS + c]);
            }
            CP_COMMIT();
        }
        if (tid < 64) { m_sh[tid] = -1e30f; l_sh[tid] = 0.f; }

        CP_WAIT0();
        __syncthreads();

        // Q fragments -> registers (whole phase). scale*log2e pre-folded.
        unsigned qa[8][4];
        {
            const __half* qbase = &Qs[(rg * 16 + (lg & 1) * 8 + lr) * QSTRH + (lg >> 1) * 8];
#pragma unroll
            for (int ks = 0; ks < 8; ks++)
                ldsm4(qa[ks][0], qa[ks][1], qa[ks][2], qa[ks][3], qbase + ks * 16);
        }

        float o[8][4];
#pragma unroll
        for (int f = 0; f < 8; f++) { o[f][0] = o[f][1] = o[f][2] = o[f][3] = 0.f; }

        for (int j = 0; j <= qi; j++) {
            const int cur = j & 1;
            __half* Ks = Ksb + cur * 64 * QSTRH;
            __half* Vs = Vsb + cur * 64 * QSTRH;

            if (j > 0) { CP_WAIT0(); }
            __syncthreads();

            if (j < qi) {
                const __half* kg = kb + (size_t)(j + 1) * 64 * HS;
                const __half* vg = vb + (size_t)(j + 1) * 64 * HS;
                __half* Kn = Ksb + (1 - cur) * 64 * QSTRH;
                __half* Vn = Vsb + (1 - cur) * 64 * QSTRH;
#pragma unroll
                for (int it = 0; it < 4; it++) {
                    int ch = tid + it * 256;
                    int r = ch >> 4, c = (ch & 15) * 8;
                    cpa16h(&Kn[r * QSTRH + c], &kg[(size_t)r * HS + c]);
                    cpa16h(&Vn[r * QSTRH + c], &vg[(size_t)r * HS + c]);
                }
                CP_COMMIT();
            }

            // ---- S = Q K^T ----
            float s[4][4];
#pragma unroll
            for (int f = 0; f < 4; f++) { s[f][0] = s[f][1] = s[f][2] = s[f][3] = 0.f; }
            {
                const __half* kbase = &Ks[(half * 32 + (lg >> 1) * 8 + lr) * QSTRH + (lg & 1) * 8];
#pragma unroll
                for (int ks = 0; ks < 8; ks++) {
#pragma unroll
                    for (int fp = 0; fp < 2; fp++) {
                        unsigned kb0, kb1, kb2, kb3;
                        ldsm4(kb0, kb1, kb2, kb3, kbase + fp * 16 * QSTRH + ks * 16);
                        mma16(s[fp * 2],     qa[ks][0], qa[ks][1], qa[ks][2], qa[ks][3], kb0, kb1);
                        mma16(s[fp * 2 + 1], qa[ks][0], qa[ks][1], qa[ks][2], qa[ks][3], kb2, kb3);
                    }
                }
            }

            // Causal mask (diagonal tile)
            if (j == qi) {
#pragma unroll
                for (int f = 0; f < 4; f++) {
                    int c = half * 32 + f * 8 + 2 * (lane & 3);
                    if (c     > r0) s[f][0] = -1e30f;
                    if (c + 1 > r0) s[f][1] = -1e30f;
                    if (c     > r1) s[f][2] = -1e30f;
                    if (c + 1 > r1) s[f][3] = -1e30f;
                }
            }

            // Row max (per half)
            float rm0 = -1e30f, rm1 = -1e30f;
#pragma unroll
            for (int f = 0; f < 4; f++) {
                rm0 = fmaxf(rm0, fmaxf(s[f][0], s[f][1]));
                rm1 = fmaxf(rm1, fmaxf(s[f][2], s[f][3]));
            }
            rm0 = fmaxf(rm0, __shfl_xor_sync(0xffffffffu, rm0, 1));
            rm0 = fmaxf(rm0, __shfl_xor_sync(0xffffffffu, rm0, 2));
            rm1 = fmaxf(rm1, __shfl_xor_sync(0xffffffffu, rm1, 1));
            rm1 = fmaxf(rm1, __shfl_xor_sync(0xffffffffu, rm1, 2));
            if ((lane & 3) == 0) {
                pmax[half * 64 + r0] = rm0;
                pmax[half * 64 + r1] = rm1;
            }
            PAIR_BAR(rg);

            // Online softmax (ex2 domain); P -> fp16 regs + smem
            float mold0 = m_sh[r0], mold1 = m_sh[r1];
            float mn0 = fmaxf(mold0, fmaxf(pmax[r0], pmax[64 + r0]));
            float mn1 = fmaxf(mold1, fmaxf(pmax[r1], pmax[64 + r1]));
            float f0 = fexp2(mold0 - mn0), f1 = fexp2(mold1 - mn1);
            float sum0 = 0.f, sum1 = 0.f;
            unsigned own_a[2][4];
#pragma unroll
            for (int f = 0; f < 4; f++) {
                int c = half * 32 + f * 8 + 2 * (lane & 3);
                float p00 = fexp2(s[f][0] - mn0), p01 = fexp2(s[f][1] - mn0);
                float p10 = fexp2(s[f][2] - mn1), p11 = fexp2(s[f][3] - mn1);
                sum0 += p00 + p01; sum1 += p10 + p11;
                unsigned h2a = ph2(p00, p01);
                unsigned h2b = ph2(p10, p11);
                *(unsigned*)&Ps[r0 * PSTRH + c] = h2a;
                *(unsigned*)&Ps[r1 * PSTRH + c] = h2b;
                own_a[f >> 1][(f & 1) * 2]     = h2a;
                own_a[f >> 1][(f & 1) * 2 + 1] = h2b;
            }
            sum0 += __shfl_xor_sync(0xffffffffu, sum0, 1);
            sum0 += __shfl_xor_sync(0xffffffffu, sum0, 2);
            sum1 += __shfl_xor_sync(0xffffffffu, sum1, 1);
            sum1 += __shfl_xor_sync(0xffffffffu, sum1, 2);
            if ((lane & 3) == 0) {
                psum[half * 64 + r0] = sum0;
                psum[half * 64 + r1] = sum1;
            }

            // Rescale O
#pragma unroll
            for (int f = 0; f < 8; f++) {
                o[f][0] *= f0; o[f][1] *= f0; o[f][2] *= f1; o[f][3] *= f1;
            }
            PAIR_BAR(rg);

            // Stats update (pair-local)
            if (half == 0 && (lane & 3) == 0) {
#pragma unroll
                for (int rr = 0; rr < 2; rr++) {
                    int r = rr ? r1 : r0;
                    float mo = m_sh[r];
                    float mn = fmaxf(mo, fmaxf(pmax[r], pmax[64 + r]));
                    l_sh[r] = l_sh[r] * fexp2(mo - mn) + psum[r] + psum[64 + r];
                    m_sh[r] = mn;
                }
            }

            // ---- O += P V ----
            {
                const __half* vbase = &Vs[((lg & 1) * 8 + lr) * QSTRH + half * 64 + (lg >> 1) * 8];
                const __half* pbase = &Ps[(rg * 16 + (lg & 1) * 8 + lr) * PSTRH + (lg >> 1) * 8];
#pragma unroll
                for (int gs = 0; gs < 4; gs++) {
                    unsigned a0, a1, a2, a3;
                    if ((gs >> 1) == half) {
                        int loc = gs & 1;
                        a0 = own_a[loc][0]; a1 = own_a[loc][1];
                        a2 = own_a[loc][2]; a3 = own_a[loc][3];
                    } else {
                        ldsm4(a0, a1, a2, a3, pbase + gs * 16);
                    }
#pragma unroll
                    for (int np = 0; np < 4; np++) {
                        unsigned vb0, vb1, vb2, vb3;
                        ldsm4t(vb0, vb1, vb2, vb3, vbase + gs * 16 * QSTRH + np * 16);
                        mma16(o[np * 2],     a0, a1, a2, a3, vb0, vb1);
                        mma16(o[np * 2 + 1], a0, a1, a2, a3, vb2, vb3);
                    }
                }
            }
        }

        // Normalize and store
        PAIR_BAR(rg);
        float li0 = 1.f / l_sh[r0];
        float li1 = 1.f / l_sh[r1];
        float* ob = out + ((size_t)b * TT + (size_t)qi * 64) * HS;
#pragma unroll
        for (int f = 0; f < 8; f++) {
            int c = half * 64 + f * 8 + 2 * (lane & 3);
            *(float2*)&ob[(size_t)r0 * HS + c] = make_float2(o[f][0] * li0, o[f][1] * li0);
            *(float2*)&ob[(size_t)r1 * HS + c] = make_float2(o[f][2] * li1, o[f][3] * li1);
        }
    }
}

// ----------------------------------------------------------------------------
// Launcher
// ----------------------------------------------------------------------------
extern "C" void kernel_launch(void* const* d_in, const int* in_sizes, int n_in,
                              void* d_out, int out_size)
{
    const float* x  = (const float*)d_in[0];
    const float* Wq = (const float*)d_in[1];
    const float* Wk = (const float*)d_in[2];
    const float* Wv = (const float*)d_in[3];
    float* out = (float*)d_out;

    dim3 pg(MM / 128, 3);
    proj_kernel<<<pg, 256>>>(x, Wq, Wk, Wv);

    cudaFuncSetAttribute(attn_kernel,
                         cudaFuncAttributeMaxDynamicSharedMemorySize,
                         ATTN_SMEM_BYTES);
    dim3 ag(32, BB);
    attn_kernel<<<ag, 256, ATTN_SMEM_BYTES>>>(out);
}